// round 2
// baseline (speedup 1.0000x reference)
#include <cuda_runtime.h>
#include <cuda_bf16.h>

#define B_ 4
#define S_ 2048
#define D_ 1024
#define H_ 16
#define E_ 64
#define M_ (B_*S_)   // 8192

// Scratch (allocation-free rule: __device__ globals)
__device__ float g_Q[(size_t)B_*H_*S_*E_];   // (B,H,S,E)
__device__ float g_K[(size_t)B_*H_*S_*E_];   // (B,H,S,E)
__device__ float g_V[(size_t)B_*H_*S_*E_];   // (B,H,S,E)
__device__ float g_Z[(size_t)B_*S_*H_*E_];   // (B,S,H*E)

// ---------------------------------------------------------------------------
// QKV projection: out[b,h,s,e] = sum_d x[b,s,d]*W[h,d,e] + bias[h,e]
// GEMM M=8192 (b,s), N per head = 64, K=1024. BN tile = 64 == one head.
// BM=128, BN=64, BK=16. 256 threads, 8x4 microtile.
// ---------------------------------------------------------------------------
__global__ __launch_bounds__(256) void proj_kernel(
    const float* __restrict__ X, const float* __restrict__ W,
    const float* __restrict__ bias, int sel)
{
    __shared__ float As[16*128];   // [k][m]
    __shared__ float Bs[16*64];    // [k][n]
    float* out = (sel == 0) ? g_Q : (sel == 1) ? g_K : g_V;

    const int tid = threadIdx.x;
    const int m0 = blockIdx.x * 128;
    const int h  = blockIdx.y;
    const float* Wh = W + (size_t)h * D_ * E_;

    const int tr = tid >> 4;     // 0..15 (8 rows each)
    const int tc = tid & 15;     // 0..15 (4 cols each)

    const int a_row = tid >> 2;  // 0..63, +64 for second f4
    const int a_c4  = tid & 3;
    const int b_r   = tid >> 4;  // 0..15 (k)
    const int b_c4  = tid & 15;  // 0..15 (n/4)

    float acc[8][4];
#pragma unroll
    for (int i = 0; i < 8; ++i)
#pragma unroll
        for (int j = 0; j < 4; ++j) acc[i][j] = 0.f;

    for (int k0 = 0; k0 < D_; k0 += 16) {
#pragma unroll
        for (int p = 0; p < 2; ++p) {
            int row = a_row + p*64;
            float4 v = *(const float4*)(X + (size_t)(m0+row)*D_ + k0 + a_c4*4);
            As[(a_c4*4+0)*128 + row] = v.x;
            As[(a_c4*4+1)*128 + row] = v.y;
            As[(a_c4*4+2)*128 + row] = v.z;
            As[(a_c4*4+3)*128 + row] = v.w;
        }
        {
            float4 v = *(const float4*)(Wh + (size_t)(k0+b_r)*E_ + b_c4*4);
            *(float4*)&Bs[b_r*64 + b_c4*4] = v;
        }
        __syncthreads();
#pragma unroll
        for (int k = 0; k < 16; ++k) {
            float4 a0 = *(float4*)&As[k*128 + tr*8];
            float4 a1 = *(float4*)&As[k*128 + tr*8 + 4];
            float4 bv = *(float4*)&Bs[k*64 + tc*4];
            float a[8] = {a0.x,a0.y,a0.z,a0.w,a1.x,a1.y,a1.z,a1.w};
            float bb[4] = {bv.x,bv.y,bv.z,bv.w};
#pragma unroll
            for (int i = 0; i < 8; ++i)
#pragma unroll
                for (int j = 0; j < 4; ++j) acc[i][j] += a[i]*bb[j];
        }
        __syncthreads();
    }

    const float4 bi = *(const float4*)&bias[h*E_ + tc*4];
#pragma unroll
    for (int i = 0; i < 8; ++i) {
        int m = m0 + tr*8 + i;
        int bidx = m >> 11;            // m / S_
        int s    = m & (S_-1);
        float* orow = out + ((size_t)(bidx*H_ + h)*S_ + s)*E_;
        float4 r;
        r.x = acc[i][0] + bi.x; r.y = acc[i][1] + bi.y;
        r.z = acc[i][2] + bi.z; r.w = acc[i][3] + bi.w;
        *(float4*)&orow[tc*4] = r;
    }
}

// ---------------------------------------------------------------------------
// Flash attention (causal). Block = (64 queries) x (b,h). 256 threads,
// 4x4 microtile over the 64x64 score tile. Online softmax, fp32.
// ---------------------------------------------------------------------------
#define ATT_SMEM_FLOATS (64*64 + 64*65 + 64*64 + 64*64)
#define ATT_SMEM_BYTES  (ATT_SMEM_FLOATS*4)

__global__ __launch_bounds__(256) void att_kernel()
{
    extern __shared__ float sm[];
    float* Qs = sm;               // [64][64]
    float* Ks = sm + 64*64;       // [64][65]  padded (col-indexed reads)
    float* Vs = Ks + 64*65;       // [64][64]
    float* Ps = Vs + 64*64;       // [64][64]

    const int tid = threadIdx.x;
    const int qt  = gridDim.x - 1 - blockIdx.x;   // big tiles first
    const int h   = blockIdx.y;
    const int b   = blockIdx.z;
    const int tr  = tid >> 4;   // row group (4 rows)
    const int tc  = tid & 15;   // col group (4 cols)

    const size_t bh = (size_t)(b*H_ + h) * S_;
    const float* Qb = g_Q + (bh + (size_t)qt*64) * E_;

    // Load Q tile (contiguous 4096 floats)
#pragma unroll
    for (int p = 0; p < 4; ++p) {
        int f = tid + 256*p;
        int row = f >> 4, d4 = f & 15;
        *(float4*)&Qs[row*64 + d4*4] = *(const float4*)(Qb + row*64 + d4*4);
    }

    float m_i[4], l_i[4], O[4][4];
#pragma unroll
    for (int i = 0; i < 4; ++i) {
        m_i[i] = -1e30f; l_i[i] = 0.f;
#pragma unroll
        for (int j = 0; j < 4; ++j) O[i][j] = 0.f;
    }

    for (int t = 0; t <= qt; ++t) {
        const float* Kb = g_K + (bh + (size_t)t*64) * E_;
        const float* Vb = g_V + (bh + (size_t)t*64) * E_;
        __syncthreads();   // previous iteration consumers done
#pragma unroll
        for (int p = 0; p < 4; ++p) {
            int f = tid + 256*p;
            int row = f >> 4, d4 = f & 15;
            float4 kv = *(const float4*)(Kb + row*64 + d4*4);
            Ks[row*65 + d4*4 + 0] = kv.x;
            Ks[row*65 + d4*4 + 1] = kv.y;
            Ks[row*65 + d4*4 + 2] = kv.z;
            Ks[row*65 + d4*4 + 3] = kv.w;
            *(float4*)&Vs[row*64 + d4*4] = *(const float4*)(Vb + row*64 + d4*4);
        }
        __syncthreads();

        // S = Q K^T
        float sv[4][4];
#pragma unroll
        for (int i = 0; i < 4; ++i)
#pragma unroll
            for (int j = 0; j < 4; ++j) sv[i][j] = 0.f;
#pragma unroll 8
        for (int d = 0; d < 64; ++d) {
            float q[4], kk[4];
#pragma unroll
            for (int i = 0; i < 4; ++i) q[i]  = Qs[(tr*4+i)*64 + d];
#pragma unroll
            for (int j = 0; j < 4; ++j) kk[j] = Ks[(tc*4+j)*65 + d];
#pragma unroll
            for (int i = 0; i < 4; ++i)
#pragma unroll
                for (int j = 0; j < 4; ++j) sv[i][j] += q[i]*kk[j];
        }

        // scale + causal mask (diagonal tile only)
#pragma unroll
        for (int i = 0; i < 4; ++i)
#pragma unroll
            for (int j = 0; j < 4; ++j) {
                float s = sv[i][j] * 0.125f;
                if (t == qt && (tc*4+j) > (tr*4+i)) s = -1e30f;
                sv[i][j] = s;
            }

        // online softmax update
#pragma unroll
        for (int i = 0; i < 4; ++i) {
            float rm = fmaxf(fmaxf(sv[i][0], sv[i][1]), fmaxf(sv[i][2], sv[i][3]));
#pragma unroll
            for (int mk = 8; mk >= 1; mk >>= 1)
                rm = fmaxf(rm, __shfl_xor_sync(0xffffffffu, rm, mk));
            float mnew = fmaxf(m_i[i], rm);
            float corr = __expf(m_i[i] - mnew);
            float rs = 0.f;
#pragma unroll
            for (int j = 0; j < 4; ++j) {
                sv[i][j] = __expf(sv[i][j] - mnew);
                rs += sv[i][j];
            }
#pragma unroll
            for (int mk = 8; mk >= 1; mk >>= 1)
                rs += __shfl_xor_sync(0xffffffffu, rs, mk);
            l_i[i] = l_i[i]*corr + rs;
            m_i[i] = mnew;
#pragma unroll
            for (int j = 0; j < 4; ++j) O[i][j] *= corr;
            *(float4*)&Ps[(tr*4+i)*64 + tc*4] =
                make_float4(sv[i][0], sv[i][1], sv[i][2], sv[i][3]);
        }
        __syncthreads();

        // O += P V
#pragma unroll 8
        for (int kk = 0; kk < 64; ++kk) {
            float4 v4 = *(float4*)&Vs[kk*64 + tc*4];
            float p[4];
#pragma unroll
            for (int i = 0; i < 4; ++i) p[i] = Ps[(tr*4+i)*64 + kk];
#pragma unroll
            for (int i = 0; i < 4; ++i) {
                O[i][0] += p[i]*v4.x; O[i][1] += p[i]*v4.y;
                O[i][2] += p[i]*v4.z; O[i][3] += p[i]*v4.w;
            }
        }
    }

    // write z (B,S,H*E)
#pragma unroll
    for (int i = 0; i < 4; ++i) {
        float inv = 1.0f / l_i[i];
        int q = qt*64 + tr*4 + i;
        float* zr = g_Z + (size_t)(b*S_ + q)*(H_*E_) + h*E_;
        float4 o;
        o.x = O[i][0]*inv; o.y = O[i][1]*inv;
        o.z = O[i][2]*inv; o.w = O[i][3]*inv;
        *(float4*)&zr[tc*4] = o;
    }
}

// ---------------------------------------------------------------------------
// Output projection: out[m, d] = sum_{he} z[m, he] * W_O[he, d] + b_O[d]
// W_O is (H,DH,D) contiguous == (1024,1024) row-major. Same tiling as proj.
// ---------------------------------------------------------------------------
__global__ __launch_bounds__(256) void outproj_kernel(
    const float* __restrict__ WO, const float* __restrict__ bO,
    float* __restrict__ out)
{
    __shared__ float As[16*128];
    __shared__ float Bs[16*64];

    const int tid = threadIdx.x;
    const int m0 = blockIdx.x * 128;
    const int n0 = blockIdx.y * 64;

    const int tr = tid >> 4;
    const int tc = tid & 15;
    const int a_row = tid >> 2;
    const int a_c4  = tid & 3;
    const int b_r   = tid >> 4;
    const int b_c4  = tid & 15;

    float acc[8][4];
#pragma unroll
    for (int i = 0; i < 8; ++i)
#pragma unroll
        for (int j = 0; j < 4; ++j) acc[i][j] = 0.f;

    for (int k0 = 0; k0 < H_*E_; k0 += 16) {
#pragma unroll
        for (int p = 0; p < 2; ++p) {
            int row = a_row + p*64;
            float4 v = *(const float4*)(g_Z + (size_t)(m0+row)*(H_*E_) + k0 + a_c4*4);
            As[(a_c4*4+0)*128 + row] = v.x;
            As[(a_c4*4+1)*128 + row] = v.y;
            As[(a_c4*4+2)*128 + row] = v.z;
            As[(a_c4*4+3)*128 + row] = v.w;
        }
        {
            float4 v = *(const float4*)(WO + (size_t)(k0+b_r)*D_ + n0 + b_c4*4);
            *(float4*)&Bs[b_r*64 + b_c4*4] = v;
        }
        __syncthreads();
#pragma unroll
        for (int k = 0; k < 16; ++k) {
            float4 a0 = *(float4*)&As[k*128 + tr*8];
            float4 a1 = *(float4*)&As[k*128 + tr*8 + 4];
            float4 bv = *(float4*)&Bs[k*64 + tc*4];
            float a[8] = {a0.x,a0.y,a0.z,a0.w,a1.x,a1.y,a1.z,a1.w};
            float bb[4] = {bv.x,bv.y,bv.z,bv.w};
#pragma unroll
            for (int i = 0; i < 8; ++i)
#pragma unroll
                for (int j = 0; j < 4; ++j) acc[i][j] += a[i]*bb[j];
        }
        __syncthreads();
    }

    const float4 bi = *(const float4*)&bO[n0 + tc*4];
#pragma unroll
    for (int i = 0; i < 8; ++i) {
        int m = m0 + tr*8 + i;
        float4 r;
        r.x = acc[i][0] + bi.x; r.y = acc[i][1] + bi.y;
        r.z = acc[i][2] + bi.z; r.w = acc[i][3] + bi.w;
        *(float4*)&out[(size_t)m*D_ + n0 + tc*4] = r;
    }
}

// ---------------------------------------------------------------------------
extern "C" void kernel_launch(void* const* d_in, const int* in_sizes, int n_in,
                              void* d_out, int out_size)
{
    const float* x   = (const float*)d_in[0];
    const float* W_Q = (const float*)d_in[1];
    const float* b_Q = (const float*)d_in[2];
    const float* W_K = (const float*)d_in[3];
    const float* b_K = (const float*)d_in[4];
    const float* W_V = (const float*)d_in[5];
    const float* b_V = (const float*)d_in[6];
    const float* W_O = (const float*)d_in[7];
    const float* b_O = (const float*)d_in[8];
    float* out = (float*)d_out;

    cudaFuncSetAttribute(att_kernel,
        cudaFuncAttributeMaxDynamicSharedMemorySize, ATT_SMEM_BYTES);

    dim3 gproj(M_/128, H_);
    proj_kernel<<<gproj, 256>>>(x, W_Q, b_Q, 0);
    proj_kernel<<<gproj, 256>>>(x, W_K, b_K, 1);
    proj_kernel<<<gproj, 256>>>(x, W_V, b_V, 2);

    dim3 gatt(S_/64, H_, B_);
    att_kernel<<<gatt, 256, ATT_SMEM_BYTES>>>();

    dim3 gout(M_/128, D_/64);
    outproj_kernel<<<gout, 256>>>(W_O, b_O, out);
}

// round 3
// speedup vs baseline: 2.3258x; 2.3258x over previous
#include <cuda_runtime.h>
#include <cuda_bf16.h>

#define B_ 4
#define S_ 2048
#define D_ 1024
#define H_ 16
#define E_ 64
#define M_ (B_*S_)   // 8192

// Scratch (allocation-free rule: __device__ globals)
__device__ float g_Q[(size_t)B_*H_*S_*E_];   // (B,H,S,E)
__device__ float g_K[(size_t)B_*H_*S_*E_];   // (B,H,S,E)
__device__ float g_V[(size_t)B_*H_*S_*E_];   // (B,H,S,E)
__device__ float g_Z[(size_t)B_*S_*H_*E_];   // (B,S,H*E)

// ---------------------------------------------------------------------------
// Helpers: tf32 round + m16n8k8 tf32 MMA
// ---------------------------------------------------------------------------
__device__ __forceinline__ float tf32r(float x) {
    asm("cvt.rna.tf32.f32 %0, %1;" : "=f"(x) : "f"(x));
    return x;
}
__device__ __forceinline__ unsigned fu(float x) { return __float_as_uint(x); }

__device__ __forceinline__ void mma8(float* d, const unsigned* a,
                                     unsigned b0, unsigned b1) {
    asm volatile(
        "mma.sync.aligned.m16n8k8.row.col.f32.tf32.tf32.f32 "
        "{%0,%1,%2,%3}, {%4,%5,%6,%7}, {%8,%9}, {%0,%1,%2,%3};\n"
        : "+f"(d[0]), "+f"(d[1]), "+f"(d[2]), "+f"(d[3])
        : "r"(a[0]), "r"(a[1]), "r"(a[2]), "r"(a[3]), "r"(b0), "r"(b1));
}

// ---------------------------------------------------------------------------
// Fused QKV projection (tf32 MMA).
// Block: 256 thr (8 warps as 4x2), tile BM=128 x (BN=64 == one head) x BK=32,
// computing Q, K, V simultaneously (X smem tile reused 3x).
// ---------------------------------------------------------------------------
#define AS_LD 136   // 128+8 : bank = 8t+g (conflict-free frag loads)
#define BS_LD 72    // 64+8

__global__ __launch_bounds__(256) void qkv_kernel(
    const float* __restrict__ X,
    const float* __restrict__ WQ, const float* __restrict__ bQ,
    const float* __restrict__ WK, const float* __restrict__ bK,
    const float* __restrict__ WV, const float* __restrict__ bV)
{
    __shared__ float As[32][AS_LD];      // [k][m]
    __shared__ float Bs[3][32][BS_LD];   // [mat][k][n]

    const int tid  = threadIdx.x;
    const int warp = tid >> 5;
    const int lane = tid & 31;
    const int t    = lane & 3;
    const int g    = lane >> 2;
    const int wm   = (warp >> 1) * 32;
    const int wn   = (warp & 1) * 32;
    const int m0   = blockIdx.x * 128;
    const int h    = blockIdx.y;

    const float* W[3] = { WQ + (size_t)h*D_*E_, WK + (size_t)h*D_*E_, WV + (size_t)h*D_*E_ };

    float acc[3][2][4][4];
#pragma unroll
    for (int m = 0; m < 3; ++m)
#pragma unroll
        for (int i = 0; i < 2; ++i)
#pragma unroll
            for (int j = 0; j < 4; ++j)
#pragma unroll
                for (int c = 0; c < 4; ++c) acc[m][i][j][c] = 0.f;

    for (int k0 = 0; k0 < D_; k0 += 32) {
        // X tile 128x32, transposed to [k][m], tf32-rounded
#pragma unroll
        for (int p = 0; p < 4; ++p) {
            int idx = tid + 256*p;          // 1024 float4s
            int row = idx >> 3, c4 = idx & 7;
            float4 v = *(const float4*)(X + (size_t)(m0+row)*D_ + k0 + c4*4);
            As[c4*4+0][row] = tf32r(v.x);
            As[c4*4+1][row] = tf32r(v.y);
            As[c4*4+2][row] = tf32r(v.z);
            As[c4*4+3][row] = tf32r(v.w);
        }
        // 3 weight tiles 32x64
#pragma unroll
        for (int mat = 0; mat < 3; ++mat) {
#pragma unroll
            for (int p = 0; p < 2; ++p) {
                int idx = tid + 256*p;       // 512 float4s
                int row = idx >> 4, c4 = idx & 15;
                float4 v = *(const float4*)(W[mat] + (size_t)(k0+row)*E_ + c4*4);
                v.x = tf32r(v.x); v.y = tf32r(v.y); v.z = tf32r(v.z); v.w = tf32r(v.w);
                *(float4*)&Bs[mat][row][c4*4] = v;
            }
        }
        __syncthreads();

#pragma unroll
        for (int k8 = 0; k8 < 4; ++k8) {
            unsigned a[2][4];
#pragma unroll
            for (int mf = 0; mf < 2; ++mf) {
                a[mf][0] = fu(As[k8*8+t  ][wm + mf*16 + g    ]);
                a[mf][1] = fu(As[k8*8+t  ][wm + mf*16 + g + 8]);
                a[mf][2] = fu(As[k8*8+t+4][wm + mf*16 + g    ]);
                a[mf][3] = fu(As[k8*8+t+4][wm + mf*16 + g + 8]);
            }
#pragma unroll
            for (int mat = 0; mat < 3; ++mat)
#pragma unroll
                for (int nf = 0; nf < 4; ++nf) {
                    unsigned b0 = fu(Bs[mat][k8*8+t  ][wn + nf*8 + g]);
                    unsigned b1 = fu(Bs[mat][k8*8+t+4][wn + nf*8 + g]);
                    mma8(acc[mat][0][nf], a[0], b0, b1);
                    mma8(acc[mat][1][nf], a[1], b0, b1);
                }
        }
        __syncthreads();
    }

    // epilogue: bias + scatter to (B,H,S,E)
    float* outp[3] = { g_Q, g_K, g_V };
    const float* biasp[3] = { bQ, bK, bV };
#pragma unroll
    for (int mat = 0; mat < 3; ++mat) {
        float* out = outp[mat];
        const float* bias = biasp[mat] + h*E_;
#pragma unroll
        for (int nf = 0; nf < 4; ++nf) {
            int col = wn + nf*8 + 2*t;
            float bi0 = bias[col], bi1 = bias[col+1];
#pragma unroll
            for (int mf = 0; mf < 2; ++mf) {
                int m = m0 + wm + mf*16 + g;
                int bidx = m >> 11, s = m & (S_-1);
                float* r0 = out + ((size_t)(bidx*H_ + h)*S_ + s)*E_ + col;
                float* r1 = r0 + 8*E_;
                *(float2*)r0 = make_float2(acc[mat][mf][nf][0] + bi0,
                                           acc[mat][mf][nf][1] + bi1);
                *(float2*)r1 = make_float2(acc[mat][mf][nf][2] + bi0,
                                           acc[mat][mf][nf][3] + bi1);
            }
        }
    }
}

// ---------------------------------------------------------------------------
// Flash attention (causal), tf32 MMA. Block = 128 queries x (b,h).
// 8 warps, each owns 16 query rows (warp-local online softmax).
// ---------------------------------------------------------------------------
#define KS_LD 68
#define VS_LD 72
#define PS_LD 68
#define ATT_SMEM_BYTES ((64*KS_LD + 64*VS_LD + 128*PS_LD)*4)

__global__ __launch_bounds__(256) void att_kernel()
{
    extern __shared__ float sm[];
    float* Ks = sm;                    // [64][68]
    float* Vs = Ks + 64*KS_LD;         // [64][72]
    float* Ps = Vs + 64*VS_LD;         // [128][68]  (also Q staging)

    const int tid  = threadIdx.x;
    const int warp = tid >> 5;
    const int lane = tid & 31;
    const int t    = lane & 3;
    const int g    = lane >> 2;
    const int wq   = warp * 16;

    const int qt = gridDim.x - 1 - blockIdx.x;   // big tiles first
    const int h  = blockIdx.y;
    const int b  = blockIdx.z;
    const size_t bh = (size_t)(b*H_ + h) * S_;
    const int q0 = qt * 128;

    // stage Q tile, then pull A-fragments into registers
    const float* Qb = g_Q + (bh + q0) * E_;
#pragma unroll
    for (int p = 0; p < 8; ++p) {
        int idx = tid + 256*p;          // 2048 float4s
        int row = idx >> 4, c4 = idx & 15;
        float4 v = *(const float4*)(Qb + row*E_ + c4*4);
        v.x = tf32r(v.x); v.y = tf32r(v.y); v.z = tf32r(v.z); v.w = tf32r(v.w);
        *(float4*)&Ps[row*PS_LD + c4*4] = v;
    }
    __syncthreads();
    unsigned qf[8][4];
#pragma unroll
    for (int d8 = 0; d8 < 8; ++d8) {
        qf[d8][0] = fu(Ps[(wq+g  )*PS_LD + d8*8 + t  ]);
        qf[d8][1] = fu(Ps[(wq+g+8)*PS_LD + d8*8 + t  ]);
        qf[d8][2] = fu(Ps[(wq+g  )*PS_LD + d8*8 + t+4]);
        qf[d8][3] = fu(Ps[(wq+g+8)*PS_LD + d8*8 + t+4]);
    }
    __syncthreads();

    float O[8][4];
#pragma unroll
    for (int nf = 0; nf < 8; ++nf)
#pragma unroll
        for (int c = 0; c < 4; ++c) O[nf][c] = 0.f;
    float mA = -1e30f, mB = -1e30f, lA = 0.f, lB = 0.f;

    const int rowA = q0 + wq + g;
    const int rowB = rowA + 8;
    const int tmax = 2*qt + 1;

    for (int kt = 0; kt <= tmax; ++kt) {
        const float* Kb = g_K + (bh + kt*64) * E_;
        const float* Vb = g_V + (bh + kt*64) * E_;
        __syncthreads();
#pragma unroll
        for (int p = 0; p < 4; ++p) {
            int idx = tid + 256*p;       // 1024 float4s
            int row = idx >> 4, c4 = idx & 15;
            float4 kv = *(const float4*)(Kb + row*E_ + c4*4);
            kv.x = tf32r(kv.x); kv.y = tf32r(kv.y); kv.z = tf32r(kv.z); kv.w = tf32r(kv.w);
            *(float4*)&Ks[row*KS_LD + c4*4] = kv;
            float4 vv = *(const float4*)(Vb + row*E_ + c4*4);
            vv.x = tf32r(vv.x); vv.y = tf32r(vv.y); vv.z = tf32r(vv.z); vv.w = tf32r(vv.w);
            *(float4*)&Vs[row*VS_LD + c4*4] = vv;
        }
        __syncthreads();

        // S = Q K^T   (64 keys x this warp's 16 rows)
        float sv[8][4];
#pragma unroll
        for (int nf = 0; nf < 8; ++nf)
#pragma unroll
            for (int c = 0; c < 4; ++c) sv[nf][c] = 0.f;
#pragma unroll
        for (int d8 = 0; d8 < 8; ++d8)
#pragma unroll
            for (int nf = 0; nf < 8; ++nf) {
                unsigned b0 = fu(Ks[(nf*8+g)*KS_LD + d8*8 + t  ]);
                unsigned b1 = fu(Ks[(nf*8+g)*KS_LD + d8*8 + t+4]);
                mma8(sv[nf], qf[d8], b0, b1);
            }

        // scale + causal mask
        const bool edge = (kt >= 2*qt);
#pragma unroll
        for (int nf = 0; nf < 8; ++nf) {
            int cb = kt*64 + nf*8 + 2*t;
            sv[nf][0] *= 0.125f; sv[nf][1] *= 0.125f;
            sv[nf][2] *= 0.125f; sv[nf][3] *= 0.125f;
            if (edge) {
                if (cb   > rowA) sv[nf][0] = -1e30f;
                if (cb+1 > rowA) sv[nf][1] = -1e30f;
                if (cb   > rowB) sv[nf][2] = -1e30f;
                if (cb+1 > rowB) sv[nf][3] = -1e30f;
            }
        }

        // warp-local online softmax (rows rowA, rowB per lane-quad)
        float rmA = -1e30f, rmB = -1e30f;
#pragma unroll
        for (int nf = 0; nf < 8; ++nf) {
            rmA = fmaxf(rmA, fmaxf(sv[nf][0], sv[nf][1]));
            rmB = fmaxf(rmB, fmaxf(sv[nf][2], sv[nf][3]));
        }
        rmA = fmaxf(rmA, __shfl_xor_sync(0xffffffffu, rmA, 1));
        rmA = fmaxf(rmA, __shfl_xor_sync(0xffffffffu, rmA, 2));
        rmB = fmaxf(rmB, __shfl_xor_sync(0xffffffffu, rmB, 1));
        rmB = fmaxf(rmB, __shfl_xor_sync(0xffffffffu, rmB, 2));

        float mnA = fmaxf(mA, rmA), mnB = fmaxf(mB, rmB);
        float corrA = __expf(mA - mnA), corrB = __expf(mB - mnB);
        float rsA = 0.f, rsB = 0.f;
#pragma unroll
        for (int nf = 0; nf < 8; ++nf) {
            float p0 = __expf(sv[nf][0] - mnA);
            float p1 = __expf(sv[nf][1] - mnA);
            float p2 = __expf(sv[nf][2] - mnB);
            float p3 = __expf(sv[nf][3] - mnB);
            rsA += p0 + p1; rsB += p2 + p3;
            *(float2*)&Ps[(wq+g  )*PS_LD + nf*8 + 2*t] = make_float2(tf32r(p0), tf32r(p1));
            *(float2*)&Ps[(wq+g+8)*PS_LD + nf*8 + 2*t] = make_float2(tf32r(p2), tf32r(p3));
        }
        rsA += __shfl_xor_sync(0xffffffffu, rsA, 1);
        rsA += __shfl_xor_sync(0xffffffffu, rsA, 2);
        rsB += __shfl_xor_sync(0xffffffffu, rsB, 1);
        rsB += __shfl_xor_sync(0xffffffffu, rsB, 2);
        lA = lA*corrA + rsA; mA = mnA;
        lB = lB*corrB + rsB; mB = mnB;
#pragma unroll
        for (int nf = 0; nf < 8; ++nf) {
            O[nf][0] *= corrA; O[nf][1] *= corrA;
            O[nf][2] *= corrB; O[nf][3] *= corrB;
        }
        __syncwarp();

        // O += P V
#pragma unroll
        for (int kk = 0; kk < 8; ++kk) {
            unsigned pa[4];
            pa[0] = fu(Ps[(wq+g  )*PS_LD + kk*8 + t  ]);
            pa[1] = fu(Ps[(wq+g+8)*PS_LD + kk*8 + t  ]);
            pa[2] = fu(Ps[(wq+g  )*PS_LD + kk*8 + t+4]);
            pa[3] = fu(Ps[(wq+g+8)*PS_LD + kk*8 + t+4]);
#pragma unroll
            for (int nf = 0; nf < 8; ++nf) {
                unsigned b0 = fu(Vs[(kk*8+t  )*VS_LD + nf*8 + g]);
                unsigned b1 = fu(Vs[(kk*8+t+4)*VS_LD + nf*8 + g]);
                mma8(O[nf], pa, b0, b1);
            }
        }
    }

    // epilogue: normalize + write z (B,S,H*E)
    float invA = 1.0f / lA, invB = 1.0f / lB;
    float* zA = g_Z + (size_t)(b*S_ + q0 + wq + g    )*(H_*E_) + h*E_;
    float* zB = g_Z + (size_t)(b*S_ + q0 + wq + g + 8)*(H_*E_) + h*E_;
#pragma unroll
    for (int nf = 0; nf < 8; ++nf) {
        int col = nf*8 + 2*t;
        *(float2*)(zA + col) = make_float2(O[nf][0]*invA, O[nf][1]*invA);
        *(float2*)(zB + col) = make_float2(O[nf][2]*invB, O[nf][3]*invB);
    }
}

// ---------------------------------------------------------------------------
// Output projection (tf32 MMA): out = Z(8192x1024) @ W_O(1024x1024) + b_O
// BM=128, BN=128, BK=32. 8 warps 4x2, warp tile 32x64.
// ---------------------------------------------------------------------------
__global__ __launch_bounds__(256) void outproj_kernel(
    const float* __restrict__ WO, const float* __restrict__ bO,
    float* __restrict__ out)
{
    __shared__ float As[32][AS_LD];   // [k][m]
    __shared__ float Bs[32][AS_LD];   // [k][n]  (stride 136)

    const int tid  = threadIdx.x;
    const int warp = tid >> 5;
    const int lane = tid & 31;
    const int t    = lane & 3;
    const int g    = lane >> 2;
    const int wm   = (warp >> 1) * 32;
    const int wn   = (warp & 1) * 64;
    const int m0   = blockIdx.x * 128;
    const int n0   = blockIdx.y * 128;

    float acc[2][8][4];
#pragma unroll
    for (int i = 0; i < 2; ++i)
#pragma unroll
        for (int j = 0; j < 8; ++j)
#pragma unroll
            for (int c = 0; c < 4; ++c) acc[i][j][c] = 0.f;

    for (int k0 = 0; k0 < D_; k0 += 32) {
#pragma unroll
        for (int p = 0; p < 4; ++p) {
            int idx = tid + 256*p;
            int row = idx >> 3, c4 = idx & 7;
            float4 v = *(const float4*)(g_Z + (size_t)(m0+row)*D_ + k0 + c4*4);
            As[c4*4+0][row] = tf32r(v.x);
            As[c4*4+1][row] = tf32r(v.y);
            As[c4*4+2][row] = tf32r(v.z);
            As[c4*4+3][row] = tf32r(v.w);
        }
#pragma unroll
        for (int p = 0; p < 4; ++p) {
            int idx = tid + 256*p;       // 32 rows x 32 float4s
            int row = idx >> 5, c4 = idx & 31;
            float4 v = *(const float4*)(WO + (size_t)(k0+row)*D_ + n0 + c4*4);
            v.x = tf32r(v.x); v.y = tf32r(v.y); v.z = tf32r(v.z); v.w = tf32r(v.w);
            *(float4*)&Bs[row][c4*4] = v;
        }
        __syncthreads();

#pragma unroll
        for (int k8 = 0; k8 < 4; ++k8) {
            unsigned a[2][4];
#pragma unroll
            for (int mf = 0; mf < 2; ++mf) {
                a[mf][0] = fu(As[k8*8+t  ][wm + mf*16 + g    ]);
                a[mf][1] = fu(As[k8*8+t  ][wm + mf*16 + g + 8]);
                a[mf][2] = fu(As[k8*8+t+4][wm + mf*16 + g    ]);
                a[mf][3] = fu(As[k8*8+t+4][wm + mf*16 + g + 8]);
            }
#pragma unroll
            for (int nf = 0; nf < 8; ++nf) {
                unsigned b0 = fu(Bs[k8*8+t  ][wn + nf*8 + g]);
                unsigned b1 = fu(Bs[k8*8+t+4][wn + nf*8 + g]);
                mma8(acc[0][nf], a[0], b0, b1);
                mma8(acc[1][nf], a[1], b0, b1);
            }
        }
        __syncthreads();
    }

#pragma unroll
    for (int nf = 0; nf < 8; ++nf) {
        int col = n0 + wn + nf*8 + 2*t;
        float bi0 = bO[col], bi1 = bO[col+1];
#pragma unroll
        for (int mf = 0; mf < 2; ++mf) {
            int m = m0 + wm + mf*16 + g;
            *(float2*)&out[(size_t)m*D_ + col] =
                make_float2(acc[mf][nf][0] + bi0, acc[mf][nf][1] + bi1);
            *(float2*)&out[(size_t)(m+8)*D_ + col] =
                make_float2(acc[mf][nf][2] + bi0, acc[mf][nf][3] + bi1);
        }
    }
}

// ---------------------------------------------------------------------------
extern "C" void kernel_launch(void* const* d_in, const int* in_sizes, int n_in,
                              void* d_out, int out_size)
{
    const float* x   = (const float*)d_in[0];
    const float* W_Q = (const float*)d_in[1];
    const float* b_Q = (const float*)d_in[2];
    const float* W_K = (const float*)d_in[3];
    const float* b_K = (const float*)d_in[4];
    const float* W_V = (const float*)d_in[5];
    const float* b_V = (const float*)d_in[6];
    const float* W_O = (const float*)d_in[7];
    const float* b_O = (const float*)d_in[8];
    float* out = (float*)d_out;

    cudaFuncSetAttribute(att_kernel,
        cudaFuncAttributeMaxDynamicSharedMemorySize, ATT_SMEM_BYTES);

    dim3 gqkv(M_/128, H_);
    qkv_kernel<<<gqkv, 256>>>(x, W_Q, b_Q, W_K, b_K, W_V, b_V);

    dim3 gatt(S_/128, H_, B_);
    att_kernel<<<gatt, 256, ATT_SMEM_BYTES>>>();

    dim3 gout(M_/128, D_/128);
    outproj_kernel<<<gout, 256>>>(W_O, b_O, out);
}

// round 5
// speedup vs baseline: 2.8009x; 1.2042x over previous
#include <cuda_runtime.h>
#include <cuda_bf16.h>

#define B_ 4
#define S_ 2048
#define D_ 1024
#define H_ 16
#define E_ 64
#define M_ (B_*S_)   // 8192

// Scratch (allocation-free rule: __device__ globals)
__device__ float g_Q[(size_t)B_*H_*S_*E_];   // (B,H,S,E)
__device__ float g_K[(size_t)B_*H_*S_*E_];   // (B,H,S,E)
__device__ float g_V[(size_t)B_*H_*S_*E_];   // (B,H,S,E)
__device__ float g_Z[(size_t)B_*S_*H_*E_];   // (B,S,H*E)

// ---------------------------------------------------------------------------
// Helpers: tf32 round + m16n8k8 tf32 MMA
// ---------------------------------------------------------------------------
__device__ __forceinline__ float tf32r(float x) {
    asm("cvt.rna.tf32.f32 %0, %1;" : "=f"(x) : "f"(x));
    return x;
}
__device__ __forceinline__ unsigned fu(float x) { return __float_as_uint(x); }

__device__ __forceinline__ void mma8(float* d, const unsigned* a,
                                     unsigned b0, unsigned b1) {
    asm volatile(
        "mma.sync.aligned.m16n8k8.row.col.f32.tf32.tf32.f32 "
        "{%0,%1,%2,%3}, {%4,%5,%6,%7}, {%8,%9}, {%0,%1,%2,%3};\n"
        : "+f"(d[0]), "+f"(d[1]), "+f"(d[2]), "+f"(d[3])
        : "r"(a[0]), "r"(a[1]), "r"(a[2]), "r"(a[3]), "r"(b0), "r"(b1));
}

#define LD_ 136   // 128+8 smem stride: conflict-free frag loads

// ---------------------------------------------------------------------------
// Fused QKV projection as 128x128x16 GEMM over N = 3*H*E = 3072.
// grid = (M/128, 24): y -> mat (y>>3), head-pair (y&7). 8 warps 4x2,
// warp tile 32x64. Register-staged prefetch pipeline, 2 CTAs/SM.
// ---------------------------------------------------------------------------
__global__ __launch_bounds__(256, 2) void qkv_kernel(
    const float* __restrict__ X,
    const float* __restrict__ WQ, const float* __restrict__ bQ,
    const float* __restrict__ WK, const float* __restrict__ bK,
    const float* __restrict__ WV, const float* __restrict__ bV)
{
    __shared__ float As[16][LD_];   // [k][m]
    __shared__ float Bs[16][LD_];   // [k-row][n]

    const int tid  = threadIdx.x;
    const int warp = tid >> 5;
    const int lane = tid & 31;
    const int t    = lane & 3;
    const int g    = lane >> 2;
    const int wm   = (warp >> 1) * 32;
    const int wn   = (warp & 1) * 64;
    const int m0   = blockIdx.x * 128;
    const int mat  = blockIdx.y >> 3;
    const int h0   = (blockIdx.y & 7) * 2;

    const float* Wm = ((mat == 0) ? WQ : (mat == 1) ? WK : WV) + (size_t)h0*D_*E_;
    const float* bias = ((mat == 0) ? bQ : (mat == 1) ? bK : bV) + h0*E_;
    float* out = (mat == 0) ? g_Q : (mat == 1) ? g_K : g_V;

    // load indices
    const int a_row = tid >> 2;          // 0..63 (+64)
    const int a_c4  = tid & 3;
    const int b_row = tid >> 5;          // 0..7 (+8)
    const int b_c4  = tid & 31;

    float4 ar[2], br[2];
    auto loadA = [&](int k0) {
#pragma unroll
        for (int p = 0; p < 2; ++p)
            ar[p] = *(const float4*)(X + (size_t)(m0 + a_row + p*64)*D_ + k0 + a_c4*4);
    };
    auto loadB = [&](int k0) {
#pragma unroll
        for (int p = 0; p < 2; ++p)
            br[p] = *(const float4*)(Wm + (size_t)(b_c4 >> 4)*D_*E_
                                     + (size_t)(k0 + b_row + p*8)*E_ + (b_c4 & 15)*4);
    };

    float acc[2][8][4];
#pragma unroll
    for (int i = 0; i < 2; ++i)
#pragma unroll
        for (int j = 0; j < 8; ++j)
#pragma unroll
            for (int c = 0; c < 4; ++c) acc[i][j][c] = 0.f;

    loadA(0); loadB(0);

    for (int k0 = 0; k0 < D_; k0 += 16) {
#pragma unroll
        for (int p = 0; p < 2; ++p) {
            int row = a_row + p*64;
            As[a_c4*4+0][row] = tf32r(ar[p].x);
            As[a_c4*4+1][row] = tf32r(ar[p].y);
            As[a_c4*4+2][row] = tf32r(ar[p].z);
            As[a_c4*4+3][row] = tf32r(ar[p].w);
        }
#pragma unroll
        for (int p = 0; p < 2; ++p) {
            float4 v = br[p];
            v.x = tf32r(v.x); v.y = tf32r(v.y); v.z = tf32r(v.z); v.w = tf32r(v.w);
            *(float4*)&Bs[b_row + p*8][b_c4*4] = v;
        }
        __syncthreads();
        if (k0 + 16 < D_) { loadA(k0+16); loadB(k0+16); }

#pragma unroll
        for (int k8 = 0; k8 < 2; ++k8) {
            unsigned a[2][4];
#pragma unroll
            for (int mf = 0; mf < 2; ++mf) {
                a[mf][0] = fu(As[k8*8+t  ][wm + mf*16 + g    ]);
                a[mf][1] = fu(As[k8*8+t  ][wm + mf*16 + g + 8]);
                a[mf][2] = fu(As[k8*8+t+4][wm + mf*16 + g    ]);
                a[mf][3] = fu(As[k8*8+t+4][wm + mf*16 + g + 8]);
            }
#pragma unroll
            for (int nf = 0; nf < 8; ++nf) {
                unsigned b0 = fu(Bs[k8*8+t  ][wn + nf*8 + g]);
                unsigned b1 = fu(Bs[k8*8+t+4][wn + nf*8 + g]);
                mma8(acc[0][nf], a[0], b0, b1);
                mma8(acc[1][nf], a[1], b0, b1);
            }
        }
        __syncthreads();
    }

    // epilogue: bias + scatter to (B,H,S,E)
#pragma unroll
    for (int nf = 0; nf < 8; ++nf) {
        int n   = wn + nf*8 + 2*t;
        int h   = n >> 6;
        int e   = n & 63;
        float bi0 = bias[h*E_ + e], bi1 = bias[h*E_ + e + 1];
        const size_t hb = (size_t)h * D_ * E_;   // head offset within out is folded below
#pragma unroll
        for (int mf = 0; mf < 2; ++mf) {
            int m = m0 + wm + mf*16 + g;
            int bidx = m >> 11, s = m & (S_-1);
            float* r0 = out + ((size_t)(bidx*H_ + h0 + h)*S_ + s)*E_ + e;
            *(float2*)r0 = make_float2(acc[mf][nf][0] + bi0, acc[mf][nf][1] + bi1);
            *(float2*)(r0 + 8*E_) = make_float2(acc[mf][nf][2] + bi0, acc[mf][nf][3] + bi1);
        }
        (void)hb;
    }
}

// ---------------------------------------------------------------------------
// Flash attention (causal), tf32 MMA. Block = 128 queries x (b,h).
// 8 warps, each owns 16 query rows. Register-staged K/V prefetch.
// ---------------------------------------------------------------------------
#define KS_LD 68
#define VS_LD 72
#define PS_LD 68
#define ATT_SMEM_BYTES ((64*KS_LD + 64*VS_LD + 128*PS_LD)*4)

__global__ __launch_bounds__(256) void att_kernel()
{
    extern __shared__ float sm[];
    float* Ks = sm;                    // [64][68]
    float* Vs = Ks + 64*KS_LD;         // [64][72]
    float* Ps = Vs + 64*VS_LD;         // [128][68]  (also Q staging)

    const int tid  = threadIdx.x;
    const int warp = tid >> 5;
    const int lane = tid & 31;
    const int t    = lane & 3;
    const int g    = lane >> 2;
    const int wq   = warp * 16;

    const int qt = gridDim.x - 1 - blockIdx.x;   // big tiles first
    const int h  = blockIdx.y;
    const int b  = blockIdx.z;
    const size_t bh = (size_t)(b*H_ + h) * S_;
    const int q0 = qt * 128;

    // stage Q tile, then pull A-fragments into registers
    const float* Qb = g_Q + (bh + q0) * E_;
#pragma unroll
    for (int p = 0; p < 8; ++p) {
        int idx = tid + 256*p;
        int row = idx >> 4, c4 = idx & 15;
        float4 v = *(const float4*)(Qb + row*E_ + c4*4);
        v.x = tf32r(v.x); v.y = tf32r(v.y); v.z = tf32r(v.z); v.w = tf32r(v.w);
        *(float4*)&Ps[row*PS_LD + c4*4] = v;
    }
    __syncthreads();
    unsigned qf[8][4];
#pragma unroll
    for (int d8 = 0; d8 < 8; ++d8) {
        qf[d8][0] = fu(Ps[(wq+g  )*PS_LD + d8*8 + t  ]);
        qf[d8][1] = fu(Ps[(wq+g+8)*PS_LD + d8*8 + t  ]);
        qf[d8][2] = fu(Ps[(wq+g  )*PS_LD + d8*8 + t+4]);
        qf[d8][3] = fu(Ps[(wq+g+8)*PS_LD + d8*8 + t+4]);
    }

    float O[8][4];
#pragma unroll
    for (int nf = 0; nf < 8; ++nf)
#pragma unroll
        for (int c = 0; c < 4; ++c) O[nf][c] = 0.f;
    float mA = -1e30f, mB = -1e30f, lA = 0.f, lB = 0.f;

    const int rowA = q0 + wq + g;
    const int rowB = rowA + 8;
    const int tmax = 2*qt + 1;

    const int l_row = tid >> 4, l_c4 = tid & 15;   // K/V load mapping
    float4 kr[4], vr[4];
    auto loadKV = [&](int kt) {
        const float* Kb = g_K + (bh + kt*64) * E_;
        const float* Vb = g_V + (bh + kt*64) * E_;
#pragma unroll
        for (int p = 0; p < 4; ++p) {
            int row = l_row + p*16;
            kr[p] = *(const float4*)(Kb + row*E_ + l_c4*4);
            vr[p] = *(const float4*)(Vb + row*E_ + l_c4*4);
        }
    };
    loadKV(0);

    for (int kt = 0; kt <= tmax; ++kt) {
        __syncthreads();   // prev tile fully consumed
#pragma unroll
        for (int p = 0; p < 4; ++p) {
            int row = l_row + p*16;
            Ks[row*KS_LD + l_c4*4 + 0] = tf32r(kr[p].x);
            Ks[row*KS_LD + l_c4*4 + 1] = tf32r(kr[p].y);
            Ks[row*KS_LD + l_c4*4 + 2] = tf32r(kr[p].z);
            Ks[row*KS_LD + l_c4*4 + 3] = tf32r(kr[p].w);
            float4 vv = vr[p];
            vv.x = tf32r(vv.x); vv.y = tf32r(vv.y); vv.z = tf32r(vv.z); vv.w = tf32r(vv.w);
            *(float4*)&Vs[row*VS_LD + l_c4*4] = vv;
        }
        __syncthreads();
        if (kt < tmax) loadKV(kt+1);   // latency hidden under MMA+softmax below

        // S = Q K^T   (64 keys x this warp's 16 rows)
        float sv[8][4];
#pragma unroll
        for (int nf = 0; nf < 8; ++nf)
#pragma unroll
            for (int c = 0; c < 4; ++c) sv[nf][c] = 0.f;
#pragma unroll
        for (int d8 = 0; d8 < 8; ++d8)
#pragma unroll
            for (int nf = 0; nf < 8; ++nf) {
                unsigned b0 = fu(Ks[(nf*8+g)*KS_LD + d8*8 + t  ]);
                unsigned b1 = fu(Ks[(nf*8+g)*KS_LD + d8*8 + t+4]);
                mma8(sv[nf], qf[d8], b0, b1);
            }

        // scale + causal mask
        const bool edge = (kt >= 2*qt);
#pragma unroll
        for (int nf = 0; nf < 8; ++nf) {
            int cb = kt*64 + nf*8 + 2*t;
            sv[nf][0] *= 0.125f; sv[nf][1] *= 0.125f;
            sv[nf][2] *= 0.125f; sv[nf][3] *= 0.125f;
            if (edge) {
                if (cb   > rowA) sv[nf][0] = -1e30f;
                if (cb+1 > rowA) sv[nf][1] = -1e30f;
                if (cb   > rowB) sv[nf][2] = -1e30f;
                if (cb+1 > rowB) sv[nf][3] = -1e30f;
            }
        }

        // warp-local online softmax
        float rmA = -1e30f, rmB = -1e30f;
#pragma unroll
        for (int nf = 0; nf < 8; ++nf) {
            rmA = fmaxf(rmA, fmaxf(sv[nf][0], sv[nf][1]));
            rmB = fmaxf(rmB, fmaxf(sv[nf][2], sv[nf][3]));
        }
        rmA = fmaxf(rmA, __shfl_xor_sync(0xffffffffu, rmA, 1));
        rmA = fmaxf(rmA, __shfl_xor_sync(0xffffffffu, rmA, 2));
        rmB = fmaxf(rmB, __shfl_xor_sync(0xffffffffu, rmB, 1));
        rmB = fmaxf(rmB, __shfl_xor_sync(0xffffffffu, rmB, 2));

        float mnA = fmaxf(mA, rmA), mnB = fmaxf(mB, rmB);
        float corrA = __expf(mA - mnA), corrB = __expf(mB - mnB);
        float rsA = 0.f, rsB = 0.f;
#pragma unroll
        for (int nf = 0; nf < 8; ++nf) {
            float p0 = __expf(sv[nf][0] - mnA);
            float p1 = __expf(sv[nf][1] - mnA);
            float p2 = __expf(sv[nf][2] - mnB);
            float p3 = __expf(sv[nf][3] - mnB);
            rsA += p0 + p1; rsB += p2 + p3;
            *(float2*)&Ps[(wq+g  )*PS_LD + nf*8 + 2*t] = make_float2(tf32r(p0), tf32r(p1));
            *(float2*)&Ps[(wq+g+8)*PS_LD + nf*8 + 2*t] = make_float2(tf32r(p2), tf32r(p3));
        }
        rsA += __shfl_xor_sync(0xffffffffu, rsA, 1);
        rsA += __shfl_xor_sync(0xffffffffu, rsA, 2);
        rsB += __shfl_xor_sync(0xffffffffu, rsB, 1);
        rsB += __shfl_xor_sync(0xffffffffu, rsB, 2);
        lA = lA*corrA + rsA; mA = mnA;
        lB = lB*corrB + rsB; mB = mnB;
#pragma unroll
        for (int nf = 0; nf < 8; ++nf) {
            O[nf][0] *= corrA; O[nf][1] *= corrA;
            O[nf][2] *= corrB; O[nf][3] *= corrB;
        }
        __syncwarp();

        // O += P V
#pragma unroll
        for (int kk = 0; kk < 8; ++kk) {
            unsigned pa[4];
            pa[0] = fu(Ps[(wq+g  )*PS_LD + kk*8 + t  ]);
            pa[1] = fu(Ps[(wq+g+8)*PS_LD + kk*8 + t  ]);
            pa[2] = fu(Ps[(wq+g  )*PS_LD + kk*8 + t+4]);
            pa[3] = fu(Ps[(wq+g+8)*PS_LD + kk*8 + t+4]);
#pragma unroll
            for (int nf = 0; nf < 8; ++nf) {
                unsigned b0 = fu(Vs[(kk*8+t  )*VS_LD + nf*8 + g]);
                unsigned b1 = fu(Vs[(kk*8+t+4)*VS_LD + nf*8 + g]);
                mma8(O[nf], pa, b0, b1);
            }
        }
    }

    // epilogue: normalize + write z (B,S,H*E)
    float invA = 1.0f / lA, invB = 1.0f / lB;
    float* zA = g_Z + (size_t)(b*S_ + q0 + wq + g    )*(H_*E_) + h*E_;
    float* zB = g_Z + (size_t)(b*S_ + q0 + wq + g + 8)*(H_*E_) + h*E_;
#pragma unroll
    for (int nf = 0; nf < 8; ++nf) {
        int col = nf*8 + 2*t;
        *(float2*)(zA + col) = make_float2(O[nf][0]*invA, O[nf][1]*invA);
        *(float2*)(zB + col) = make_float2(O[nf][2]*invB, O[nf][3]*invB);
    }
}

// ---------------------------------------------------------------------------
// Output projection (tf32 MMA): out = Z(8192x1024) @ W_O(1024x1024) + b_O
// BM=128, BN=128, BK=16, register-staged pipeline, 2 CTAs/SM.
// ---------------------------------------------------------------------------
__global__ __launch_bounds__(256, 2) void outproj_kernel(
    const float* __restrict__ WO, const float* __restrict__ bO,
    float* __restrict__ out)
{
    __shared__ float As[16][LD_];
    __shared__ float Bs[16][LD_];

    const int tid  = threadIdx.x;
    const int warp = tid >> 5;
    const int lane = tid & 31;
    const int t    = lane & 3;
    const int g    = lane >> 2;
    const int wm   = (warp >> 1) * 32;
    const int wn   = (warp & 1) * 64;
    const int m0   = blockIdx.x * 128;
    const int n0   = blockIdx.y * 128;

    const int a_row = tid >> 2;
    const int a_c4  = tid & 3;
    const int b_row = tid >> 5;
    const int b_c4  = tid & 31;

    float4 ar[2], br[2];
    auto loadA = [&](int k0) {
#pragma unroll
        for (int p = 0; p < 2; ++p)
            ar[p] = *(const float4*)(g_Z + (size_t)(m0 + a_row + p*64)*D_ + k0 + a_c4*4);
    };
    auto loadB = [&](int k0) {
#pragma unroll
        for (int p = 0; p < 2; ++p)
            br[p] = *(const float4*)(WO + (size_t)(k0 + b_row + p*8)*D_ + n0 + b_c4*4);
    };

    float acc[2][8][4];
#pragma unroll
    for (int i = 0; i < 2; ++i)
#pragma unroll
        for (int j = 0; j < 8; ++j)
#pragma unroll
            for (int c = 0; c < 4; ++c) acc[i][j][c] = 0.f;

    loadA(0); loadB(0);

    for (int k0 = 0; k0 < D_; k0 += 16) {
#pragma unroll
        for (int p = 0; p < 2; ++p) {
            int row = a_row + p*64;
            As[a_c4*4+0][row] = tf32r(ar[p].x);
            As[a_c4*4+1][row] = tf32r(ar[p].y);
            As[a_c4*4+2][row] = tf32r(ar[p].z);
            As[a_c4*4+3][row] = tf32r(ar[p].w);
        }
#pragma unroll
        for (int p = 0; p < 2; ++p) {
            float4 v = br[p];
            v.x = tf32r(v.x); v.y = tf32r(v.y); v.z = tf32r(v.z); v.w = tf32r(v.w);
            *(float4*)&Bs[b_row + p*8][b_c4*4] = v;
        }
        __syncthreads();
        if (k0 + 16 < D_) { loadA(k0+16); loadB(k0+16); }

#pragma unroll
        for (int k8 = 0; k8 < 2; ++k8) {
            unsigned a[2][4];
#pragma unroll
            for (int mf = 0; mf < 2; ++mf) {
                a[mf][0] = fu(As[k8*8+t  ][wm + mf*16 + g    ]);
                a[mf][1] = fu(As[k8*8+t  ][wm + mf*16 + g + 8]);
                a[mf][2] = fu(As[k8*8+t+4][wm + mf*16 + g    ]);
                a[mf][3] = fu(As[k8*8+t+4][wm + mf*16 + g + 8]);
            }
#pragma unroll
            for (int nf = 0; nf < 8; ++nf) {
                unsigned b0 = fu(Bs[k8*8+t  ][wn + nf*8 + g]);
                unsigned b1 = fu(Bs[k8*8+t+4][wn + nf*8 + g]);
                mma8(acc[0][nf], a[0], b0, b1);
                mma8(acc[1][nf], a[1], b0, b1);
            }
        }
        __syncthreads();
    }

#pragma unroll
    for (int nf = 0; nf < 8; ++nf) {
        int col = n0 + wn + nf*8 + 2*t;
        float bi0 = bO[col], bi1 = bO[col+1];
#pragma unroll
        for (int mf = 0; mf < 2; ++mf) {
            int m = m0 + wm + mf*16 + g;
            *(float2*)&out[(size_t)m*D_ + col] =
                make_float2(acc[mf][nf][0] + bi0, acc[mf][nf][1] + bi1);
            *(float2*)&out[(size_t)(m+8)*D_ + col] =
                make_float2(acc[mf][nf][2] + bi0, acc[mf][nf][3] + bi1);
        }
    }
}

// ---------------------------------------------------------------------------
extern "C" void kernel_launch(void* const* d_in, const int* in_sizes, int n_in,
                              void* d_out, int out_size)
{
    const float* x   = (const float*)d_in[0];
    const float* W_Q = (const float*)d_in[1];
    const float* b_Q = (const float*)d_in[2];
    const float* W_K = (const float*)d_in[3];
    const float* b_K = (const float*)d_in[4];
    const float* W_V = (const float*)d_in[5];
    const float* b_V = (const float*)d_in[6];
    const float* W_O = (const float*)d_in[7];
    const float* b_O = (const float*)d_in[8];
    float* out = (float*)d_out;

    cudaFuncSetAttribute(att_kernel,
        cudaFuncAttributeMaxDynamicSharedMemorySize, ATT_SMEM_BYTES);

    dim3 gqkv(M_/128, 24);
    qkv_kernel<<<gqkv, 256>>>(x, W_Q, b_Q, W_K, b_K, W_V, b_V);

    dim3 gatt(S_/128, H_, B_);
    att_kernel<<<gatt, 256, ATT_SMEM_BYTES>>>();

    dim3 gout(M_/128, D_/128);
    outproj_kernel<<<gout, 256>>>(W_O, b_O, out);
}

// round 9
// speedup vs baseline: 3.2247x; 1.1513x over previous
#include <cuda_runtime.h>
#include <cuda_bf16.h>
#include <cstdint>

#define B_ 4
#define S_ 2048
#define D_ 1024
#define H_ 16
#define E_ 64
#define M_ (B_*S_)   // 8192

// Scratch (allocation-free rule: __device__ globals)
__device__ float g_Q[(size_t)B_*H_*S_*E_];   // (B,H,S,E)
__device__ float g_K[(size_t)B_*H_*S_*E_];   // (B,H,S,E)
__device__ float g_V[(size_t)B_*H_*S_*E_];   // (B,H,S,E)
__device__ float g_Z[(size_t)B_*S_*H_*E_];   // (B,S,H*E)
// Pre-transposed (and tf32-rounded) weights: [h][e][k] / [n][k]
__device__ float g_WTq[(size_t)H_*E_*D_];
__device__ float g_WTk[(size_t)H_*E_*D_];
__device__ float g_WTv[(size_t)H_*E_*D_];
__device__ float g_WTo[(size_t)D_*D_];

// ---------------------------------------------------------------------------
// Helpers
// ---------------------------------------------------------------------------
__device__ __forceinline__ float tf32r(float x) {
    asm("cvt.rna.tf32.f32 %0, %1;" : "=f"(x) : "f"(x));
    return x;
}
__device__ __forceinline__ unsigned fu(float x) { return __float_as_uint(x); }

__device__ __forceinline__ void mma8(float* d, const unsigned* a,
                                     unsigned b0, unsigned b1) {
    asm volatile(
        "mma.sync.aligned.m16n8k8.row.col.f32.tf32.tf32.f32 "
        "{%0,%1,%2,%3}, {%4,%5,%6,%7}, {%8,%9}, {%0,%1,%2,%3};\n"
        : "+f"(d[0]), "+f"(d[1]), "+f"(d[2]), "+f"(d[3])
        : "r"(a[0]), "r"(a[1]), "r"(a[2]), "r"(a[3]), "r"(b0), "r"(b1));
}

__device__ __forceinline__ uint32_t smem_u32(const void* p) {
    uint32_t a;
    asm("{ .reg .u64 t; cvta.to.shared.u64 t, %1; cvt.u32.u64 %0, t; }"
        : "=r"(a) : "l"(p));
    return a;
}

#define LDSM4(r0, r1, r2, r3, addr) \
    asm volatile("ldmatrix.sync.aligned.m8n8.x4.shared.b16 {%0,%1,%2,%3}, [%4];" \
        : "=r"(r0), "=r"(r1), "=r"(r2), "=r"(r3) : "r"(addr))

// SW128 swizzle on byte offsets (rows of 128B): chunk ^= row&7
#define SWZ(x) ((x) ^ (((x) >> 3) & 0x70))

// ---------------------------------------------------------------------------
// Weight transpose + tf32 rounding: out[z][c][r] = round(in[z][r][c])
// ---------------------------------------------------------------------------
__global__ void transpose_rc(const float* __restrict__ in, float* __restrict__ out,
                             int R, int C)
{
    __shared__ float t[32][33];
    const size_t zo = (size_t)blockIdx.z * R * C;
    in  += zo; out += zo;
    int r0 = blockIdx.x*32, c0 = blockIdx.y*32;
    int tx = threadIdx.x, ty = threadIdx.y;
#pragma unroll
    for (int j = 0; j < 4; ++j)
        t[ty + 8*j][tx] = in[(size_t)(r0 + ty + 8*j)*C + c0 + tx];
    __syncthreads();
#pragma unroll
    for (int j = 0; j < 4; ++j)
        out[(size_t)(c0 + ty + 8*j)*R + r0 + tx] = tf32r(t[tx][ty + 8*j]);
}

// ---------------------------------------------------------------------------
// GEMM inner machinery (ldmatrix-based), shared by qkv / outproj.
// Block tile 128x128xBK32, 8 warps (4x2), warp tile 32x64.
// Smem: A[128][32] f32 (K-major, SW128), B[128 n][32 k] f32 (K-major, SW128).
// ---------------------------------------------------------------------------
#define GEMM_BODY(A_LOAD_EXPR, B_LOAD_EXPR, ROUND_A)                          \
    __shared__ __align__(128) float As[4096];                                 \
    __shared__ __align__(128) float Bs[4096];                                 \
    const int tid  = threadIdx.x;                                             \
    const int warp = tid >> 5;                                                \
    const int lane = tid & 31;                                                \
    const int t    = lane & 3;  (void)t;                                      \
    const int g    = lane >> 2; (void)g;                                      \
    const int wm   = (warp >> 1) * 32;                                        \
    const int wn   = (warp & 1) * 64;                                         \
    const int f_row = tid >> 3;                                               \
    const int f_c   = tid & 7;                                                \
    const uint32_t sw = (uint32_t)(lane & 7);                                 \
    const uint32_t aSel = (uint32_t)((lane >> 4) & 1);                        \
    const uint32_t bSel = (uint32_t)((lane >> 3) & 1);                        \
    const uint32_t asm_base = smem_u32(As);                                   \
    const uint32_t bsm_base = smem_u32(Bs);                                   \
    uint32_t aBase[2], bBase[4];                                              \
    _Pragma("unroll")                                                         \
    for (int mf = 0; mf < 2; ++mf)                                            \
        aBase[mf] = asm_base + (uint32_t)(wm + mf*16 + (lane & 15)) * 128u;   \
    _Pragma("unroll")                                                         \
    for (int q = 0; q < 4; ++q)                                               \
        bBase[q] = bsm_base + (uint32_t)(wn + q*16 + ((lane>>4)&1)*8          \
                                         + (lane & 7)) * 128u;                \
    float acc[2][8][4];                                                       \
    _Pragma("unroll")                                                         \
    for (int i = 0; i < 2; ++i)                                               \
        _Pragma("unroll")                                                     \
        for (int j = 0; j < 8; ++j)                                           \
            _Pragma("unroll")                                                 \
            for (int c = 0; c < 4; ++c) acc[i][j][c] = 0.f;                   \
    float4 ar[4], br[4];                                                      \
    {   int k0 = 0;                                                           \
        _Pragma("unroll")                                                     \
        for (int p = 0; p < 4; ++p) { ar[p] = (A_LOAD_EXPR); }                \
        _Pragma("unroll")                                                     \
        for (int p = 0; p < 4; ++p) { br[p] = (B_LOAD_EXPR); }                \
    }                                                                         \
    for (int kc = 0; kc < 32; ++kc) {                                         \
        _Pragma("unroll")                                                     \
        for (int p = 0; p < 4; ++p) {                                         \
            int row = f_row + 32*p;                                           \
            float4 v = ar[p];                                                 \
            if (ROUND_A) { v.x = tf32r(v.x); v.y = tf32r(v.y);                \
                           v.z = tf32r(v.z); v.w = tf32r(v.w); }              \
            *(float4*)((char*)As + SWZ((uint32_t)(row*128 + f_c*16))) = v;    \
            *(float4*)((char*)Bs + SWZ((uint32_t)(row*128 + f_c*16))) = br[p];\
        }                                                                     \
        __syncthreads();                                                      \
        if (kc < 31) {                                                        \
            int k0 = (kc + 1) * 32;                                           \
            _Pragma("unroll")                                                 \
            for (int p = 0; p < 4; ++p) { ar[p] = (A_LOAD_EXPR); }            \
            _Pragma("unroll")                                                 \
            for (int p = 0; p < 4; ++p) { br[p] = (B_LOAD_EXPR); }            \
        }                                                                     \
        _Pragma("unroll")                                                     \
        for (int k8 = 0; k8 < 4; ++k8) {                                      \
            const uint32_t ofsA = (((uint32_t)(2*k8) + aSel) ^ sw) << 4;      \
            const uint32_t ofsB = (((uint32_t)(2*k8) + bSel) ^ sw) << 4;      \
            unsigned a0[4], a1[4];                                            \
            LDSM4(a0[0], a0[1], a0[2], a0[3], aBase[0] + ofsA);               \
            LDSM4(a1[0], a1[1], a1[2], a1[3], aBase[1] + ofsA);               \
            _Pragma("unroll")                                                 \
            for (int q = 0; q < 4; ++q) {                                     \
                unsigned b0, b1, b2, b3;                                      \
                LDSM4(b0, b1, b2, b3, bBase[q] + ofsB);                       \
                mma8(acc[0][2*q],   a0, b0, b1);                              \
                mma8(acc[1][2*q],   a1, b0, b1);                              \
                mma8(acc[0][2*q+1], a0, b2, b3);                              \
                mma8(acc[1][2*q+1], a1, b2, b3);                              \
            }                                                                 \
        }                                                                     \
        __syncthreads();                                                      \
    }

// ---------------------------------------------------------------------------
// Fused QKV projection. grid (64, 24): y -> mat (y>>3), head-pair (y&7).
// ---------------------------------------------------------------------------
__global__ __launch_bounds__(256, 2) void qkv_kernel(
    const float* __restrict__ X,
    const float* __restrict__ bQ, const float* __restrict__ bK,
    const float* __restrict__ bV)
{
    const int m0  = blockIdx.x * 128;
    const int mat = blockIdx.y >> 3;
    const int h0  = (blockIdx.y & 7) * 2;
    const float* WT = ((mat==0) ? g_WTq : (mat==1) ? g_WTk : g_WTv)
                      + (size_t)h0 * E_ * D_;
    const float* bias = ((mat==0) ? bQ : (mat==1) ? bK : bV) + h0*E_;
    float* out = (mat==0) ? g_Q : (mat==1) ? g_K : g_V;

    GEMM_BODY(
        (*(const float4*)(X  + (size_t)(m0 + f_row + 32*p)*D_ + k0 + f_c*4)),
        (*(const float4*)(WT + (size_t)(f_row + 32*p)*D_      + k0 + f_c*4)),
        true)

    // epilogue: bias + scatter to (B,H,S,E)
#pragma unroll
    for (int nf = 0; nf < 8; ++nf) {
        int n = wn + nf*8 + 2*t;
        int h = n >> 6;
        int e = n & 63;
        float bi0 = bias[h*E_ + e], bi1 = bias[h*E_ + e + 1];
#pragma unroll
        for (int mf = 0; mf < 2; ++mf) {
            int m = m0 + wm + mf*16 + g;
            int bidx = m >> 11, s = m & (S_-1);
            float* r0 = out + ((size_t)(bidx*H_ + h0 + h)*S_ + s)*E_ + e;
            *(float2*)r0 = make_float2(acc[mf][nf][0] + bi0, acc[mf][nf][1] + bi1);
            *(float2*)(r0 + 8*E_) = make_float2(acc[mf][nf][2] + bi0,
                                                acc[mf][nf][3] + bi1);
        }
    }
}

// ---------------------------------------------------------------------------
// Output projection. grid (64, 8).
// ---------------------------------------------------------------------------
__global__ __launch_bounds__(256, 2) void outproj_kernel(
    const float* __restrict__ bO, float* __restrict__ outp)
{
    const int m0 = blockIdx.x * 128;
    const int n0 = blockIdx.y * 128;

    GEMM_BODY(
        (*(const float4*)(g_Z   + (size_t)(m0 + f_row + 32*p)*D_ + k0 + f_c*4)),
        (*(const float4*)(g_WTo + (size_t)(n0 + f_row + 32*p)*D_ + k0 + f_c*4)),
        true)

#pragma unroll
    for (int nf = 0; nf < 8; ++nf) {
        int col = n0 + wn + nf*8 + 2*t;
        float bi0 = bO[col], bi1 = bO[col+1];
#pragma unroll
        for (int mf = 0; mf < 2; ++mf) {
            int m = m0 + wm + mf*16 + g;
            *(float2*)&outp[(size_t)m*D_ + col] =
                make_float2(acc[mf][nf][0] + bi0, acc[mf][nf][1] + bi1);
            *(float2*)&outp[(size_t)(m+8)*D_ + col] =
                make_float2(acc[mf][nf][2] + bi0, acc[mf][nf][3] + bi1);
        }
    }
}

// ---------------------------------------------------------------------------
// Flash attention (causal), tf32 MMA — unchanged from R5 (passing baseline).
// ---------------------------------------------------------------------------
#define KS_LD 68
#define VS_LD 72
#define PS_LD 68
#define ATT_SMEM_BYTES ((64*KS_LD + 64*VS_LD + 128*PS_LD)*4)

__global__ __launch_bounds__(256) void att_kernel()
{
    extern __shared__ float sm[];
    float* Ks = sm;
    float* Vs = Ks + 64*KS_LD;
    float* Ps = Vs + 64*VS_LD;

    const int tid  = threadIdx.x;
    const int warp = tid >> 5;
    const int lane = tid & 31;
    const int t    = lane & 3;
    const int g    = lane >> 2;
    const int wq   = warp * 16;

    const int qt = gridDim.x - 1 - blockIdx.x;
    const int h  = blockIdx.y;
    const int b  = blockIdx.z;
    const size_t bh = (size_t)(b*H_ + h) * S_;
    const int q0 = qt * 128;

    const float* Qb = g_Q + (bh + q0) * E_;
#pragma unroll
    for (int p = 0; p < 8; ++p) {
        int idx = tid + 256*p;
        int row = idx >> 4, c4 = idx & 15;
        float4 v = *(const float4*)(Qb + row*E_ + c4*4);
        v.x = tf32r(v.x); v.y = tf32r(v.y); v.z = tf32r(v.z); v.w = tf32r(v.w);
        *(float4*)&Ps[row*PS_LD + c4*4] = v;
    }
    __syncthreads();
    unsigned qf[8][4];
#pragma unroll
    for (int d8 = 0; d8 < 8; ++d8) {
        qf[d8][0] = fu(Ps[(wq+g  )*PS_LD + d8*8 + t  ]);
        qf[d8][1] = fu(Ps[(wq+g+8)*PS_LD + d8*8 + t  ]);
        qf[d8][2] = fu(Ps[(wq+g  )*PS_LD + d8*8 + t+4]);
        qf[d8][3] = fu(Ps[(wq+g+8)*PS_LD + d8*8 + t+4]);
    }

    float O[8][4];
#pragma unroll
    for (int nf = 0; nf < 8; ++nf)
#pragma unroll
        for (int ccc = 0; ccc < 4; ++ccc) O[nf][ccc] = 0.f;
    float mA = -1e30f, mB = -1e30f, lA = 0.f, lB = 0.f;

    const int rowA = q0 + wq + g;
    const int rowB = rowA + 8;
    const int tmax = 2*qt + 1;

    const int l_row = tid >> 4, l_c4 = tid & 15;
    float4 kr[4], vr[4];
    auto loadKV = [&](int kt) {
        const float* Kb = g_K + (bh + kt*64) * E_;
        const float* Vb = g_V + (bh + kt*64) * E_;
#pragma unroll
        for (int p = 0; p < 4; ++p) {
            int row = l_row + p*16;
            kr[p] = *(const float4*)(Kb + row*E_ + l_c4*4);
            vr[p] = *(const float4*)(Vb + row*E_ + l_c4*4);
        }
    };
    loadKV(0);

    for (int kt = 0; kt <= tmax; ++kt) {
        __syncthreads();
#pragma unroll
        for (int p = 0; p < 4; ++p) {
            int row = l_row + p*16;
            Ks[row*KS_LD + l_c4*4 + 0] = tf32r(kr[p].x);
            Ks[row*KS_LD + l_c4*4 + 1] = tf32r(kr[p].y);
            Ks[row*KS_LD + l_c4*4 + 2] = tf32r(kr[p].z);
            Ks[row*KS_LD + l_c4*4 + 3] = tf32r(kr[p].w);
            float4 vv = vr[p];
            vv.x = tf32r(vv.x); vv.y = tf32r(vv.y); vv.z = tf32r(vv.z); vv.w = tf32r(vv.w);
            *(float4*)&Vs[row*VS_LD + l_c4*4] = vv;
        }
        __syncthreads();
        if (kt < tmax) loadKV(kt+1);

        float sv[8][4];
#pragma unroll
        for (int nf = 0; nf < 8; ++nf)
#pragma unroll
            for (int ccc = 0; ccc < 4; ++ccc) sv[nf][ccc] = 0.f;
#pragma unroll
        for (int d8 = 0; d8 < 8; ++d8)
#pragma unroll
            for (int nf = 0; nf < 8; ++nf) {
                unsigned b0 = fu(Ks[(nf*8+g)*KS_LD + d8*8 + t  ]);
                unsigned b1 = fu(Ks[(nf*8+g)*KS_LD + d8*8 + t+4]);
                mma8(sv[nf], qf[d8], b0, b1);
            }

        const bool edge = (kt >= 2*qt);
#pragma unroll
        for (int nf = 0; nf < 8; ++nf) {
            int cb = kt*64 + nf*8 + 2*t;
            sv[nf][0] *= 0.125f; sv[nf][1] *= 0.125f;
            sv[nf][2] *= 0.125f; sv[nf][3] *= 0.125f;
            if (edge) {
                if (cb   > rowA) sv[nf][0] = -1e30f;
                if (cb+1 > rowA) sv[nf][1] = -1e30f;
                if (cb   > rowB) sv[nf][2] = -1e30f;
                if (cb+1 > rowB) sv[nf][3] = -1e30f;
            }
        }

        float rmA = -1e30f, rmB = -1e30f;
#pragma unroll
        for (int nf = 0; nf < 8; ++nf) {
            rmA = fmaxf(rmA, fmaxf(sv[nf][0], sv[nf][1]));
            rmB = fmaxf(rmB, fmaxf(sv[nf][2], sv[nf][3]));
        }
        rmA = fmaxf(rmA, __shfl_xor_sync(0xffffffffu, rmA, 1));
        rmA = fmaxf(rmA, __shfl_xor_sync(0xffffffffu, rmA, 2));
        rmB = fmaxf(rmB, __shfl_xor_sync(0xffffffffu, rmB, 1));
        rmB = fmaxf(rmB, __shfl_xor_sync(0xffffffffu, rmB, 2));

        float mnA = fmaxf(mA, rmA), mnB = fmaxf(mB, rmB);
        float corrA = __expf(mA - mnA), corrB = __expf(mB - mnB);
        float rsA = 0.f, rsB = 0.f;
#pragma unroll
        for (int nf = 0; nf < 8; ++nf) {
            float p0 = __expf(sv[nf][0] - mnA);
            float p1 = __expf(sv[nf][1] - mnA);
            float p2 = __expf(sv[nf][2] - mnB);
            float p3 = __expf(sv[nf][3] - mnB);
            rsA += p0 + p1; rsB += p2 + p3;
            *(float2*)&Ps[(wq+g  )*PS_LD + nf*8 + 2*t] = make_float2(tf32r(p0), tf32r(p1));
            *(float2*)&Ps[(wq+g+8)*PS_LD + nf*8 + 2*t] = make_float2(tf32r(p2), tf32r(p3));
        }
        rsA += __shfl_xor_sync(0xffffffffu, rsA, 1);
        rsA += __shfl_xor_sync(0xffffffffu, rsA, 2);
        rsB += __shfl_xor_sync(0xffffffffu, rsB, 1);
        rsB += __shfl_xor_sync(0xffffffffu, rsB, 2);
        lA = lA*corrA + rsA; mA = mnA;
        lB = lB*corrB + rsB; mB = mnB;
#pragma unroll
        for (int nf = 0; nf < 8; ++nf) {
            O[nf][0] *= corrA; O[nf][1] *= corrA;
            O[nf][2] *= corrB; O[nf][3] *= corrB;
        }
        __syncwarp();

#pragma unroll
        for (int kk = 0; kk < 8; ++kk) {
            unsigned pa[4];
            pa[0] = fu(Ps[(wq+g  )*PS_LD + kk*8 + t  ]);
            pa[1] = fu(Ps[(wq+g+8)*PS_LD + kk*8 + t  ]);
            pa[2] = fu(Ps[(wq+g  )*PS_LD + kk*8 + t+4]);
            pa[3] = fu(Ps[(wq+g+8)*PS_LD + kk*8 + t+4]);
#pragma unroll
            for (int nf = 0; nf < 8; ++nf) {
                unsigned b0 = fu(Vs[(kk*8+t  )*VS_LD + nf*8 + g]);
                unsigned b1 = fu(Vs[(kk*8+t+4)*VS_LD + nf*8 + g]);
                mma8(O[nf], pa, b0, b1);
            }
        }
    }

    float invA = 1.0f / lA, invB = 1.0f / lB;
    float* zA = g_Z + (size_t)(b*S_ + q0 + wq + g    )*(H_*E_) + h*E_;
    float* zB = g_Z + (size_t)(b*S_ + q0 + wq + g + 8)*(H_*E_) + h*E_;
#pragma unroll
    for (int nf = 0; nf < 8; ++nf) {
        int col = nf*8 + 2*t;
        *(float2*)(zA + col) = make_float2(O[nf][0]*invA, O[nf][1]*invA);
        *(float2*)(zB + col) = make_float2(O[nf][2]*invB, O[nf][3]*invB);
    }
}

// ---------------------------------------------------------------------------
extern "C" void kernel_launch(void* const* d_in, const int* in_sizes, int n_in,
                              void* d_out, int out_size)
{
    const float* x   = (const float*)d_in[0];
    const float* W_Q = (const float*)d_in[1];
    const float* b_Q = (const float*)d_in[2];
    const float* W_K = (const float*)d_in[3];
    const float* b_K = (const float*)d_in[4];
    const float* W_V = (const float*)d_in[5];
    const float* b_V = (const float*)d_in[6];
    const float* W_O = (const float*)d_in[7];
    const float* b_O = (const float*)d_in[8];
    float* out = (float*)d_out;

    cudaFuncSetAttribute(att_kernel,
        cudaFuncAttributeMaxDynamicSharedMemorySize, ATT_SMEM_BYTES);

    // Resolve device-global scratch addresses (host-side symbol addresses).
    float *wtq, *wtk, *wtv, *wto;
    cudaGetSymbolAddress((void**)&wtq, g_WTq);
    cudaGetSymbolAddress((void**)&wtk, g_WTk);
    cudaGetSymbolAddress((void**)&wtv, g_WTv);
    cudaGetSymbolAddress((void**)&wto, g_WTo);

    // Pre-transpose + tf32-round weights (per-head [D][E] -> [E][D]; WO 1024^2)
    dim3 tb(32, 8);
    transpose_rc<<<dim3(32, 2, 16), tb>>>(W_Q, wtq, D_, E_);
    transpose_rc<<<dim3(32, 2, 16), tb>>>(W_K, wtk, D_, E_);
    transpose_rc<<<dim3(32, 2, 16), tb>>>(W_V, wtv, D_, E_);
    transpose_rc<<<dim3(32, 32, 1), tb>>>(W_O, wto, D_, D_);

    dim3 gqkv(M_/128, 24);
    qkv_kernel<<<gqkv, 256>>>(x, b_Q, b_K, b_V);

    dim3 gatt(S_/128, H_, B_);
    att_kernel<<<gatt, 256, ATT_SMEM_BYTES>>>();

    dim3 gout(M_/128, D_/128);
    outproj_kernel<<<gout, 256>>>(b_O, out);
}

// round 11
// speedup vs baseline: 3.3107x; 1.0267x over previous
#include <cuda_runtime.h>
#include <cuda_bf16.h>
#include <cstdint>

#define B_ 4
#define S_ 2048
#define D_ 1024
#define H_ 16
#define E_ 64
#define M_ (B_*S_)   // 8192

// Scratch (allocation-free rule: __device__ globals)
__device__ float g_Q [(size_t)B_*H_*S_*E_];  // (B,H,S,E)   (pre-scaled by 1/8)
__device__ float g_K [(size_t)B_*H_*S_*E_];  // (B,H,S,E)
__device__ float g_Vt[(size_t)B_*H_*E_*S_];  // (B,H,E,S)   V transposed
__device__ float g_Z [(size_t)B_*S_*H_*E_];  // (B,S,H*E)
// Pre-transposed (and tf32-rounded) weights: [h][e][k] / [n][k]
__device__ float g_WTq[(size_t)H_*E_*D_];
__device__ float g_WTk[(size_t)H_*E_*D_];
__device__ float g_WTv[(size_t)H_*E_*D_];
__device__ float g_WTo[(size_t)D_*D_];

// ---------------------------------------------------------------------------
// Helpers
// ---------------------------------------------------------------------------
__device__ __forceinline__ float tf32r(float x) {
    asm("cvt.rna.tf32.f32 %0, %1;" : "=f"(x) : "f"(x));
    return x;
}
__device__ __forceinline__ unsigned fu(float x) { return __float_as_uint(x); }

__device__ __forceinline__ void mma8(float* d, const unsigned* a,
                                     unsigned b0, unsigned b1) {
    asm volatile(
        "mma.sync.aligned.m16n8k8.row.col.f32.tf32.tf32.f32 "
        "{%0,%1,%2,%3}, {%4,%5,%6,%7}, {%8,%9}, {%0,%1,%2,%3};\n"
        : "+f"(d[0]), "+f"(d[1]), "+f"(d[2]), "+f"(d[3])
        : "r"(a[0]), "r"(a[1]), "r"(a[2]), "r"(a[3]), "r"(b0), "r"(b1));
}

__device__ __forceinline__ uint32_t smem_u32(const void* p) {
    uint32_t a;
    asm("{ .reg .u64 t; cvta.to.shared.u64 t, %1; cvt.u32.u64 %0, t; }"
        : "=r"(a) : "l"(p));
    return a;
}

#define LDSM4(r0, r1, r2, r3, addr) \
    asm volatile("ldmatrix.sync.aligned.m8n8.x4.shared.b16 {%0,%1,%2,%3}, [%4];" \
        : "=r"(r0), "=r"(r1), "=r"(r2), "=r"(r3) : "r"(addr))

// SW128 swizzle on byte offsets (rows of 128B)
#define SWZ(x) ((x) ^ (((x) >> 3) & 0x70))

// ---------------------------------------------------------------------------
// Weight transpose + tf32 rounding: out[z][c][r] = round(in[z][r][c])
// ---------------------------------------------------------------------------
__global__ void transpose_rc(const float* __restrict__ in, float* __restrict__ out,
                             int R, int C)
{
    __shared__ float t[32][33];
    const size_t zo = (size_t)blockIdx.z * R * C;
    in  += zo; out += zo;
    int r0 = blockIdx.x*32, c0 = blockIdx.y*32;
    int tx = threadIdx.x, ty = threadIdx.y;
#pragma unroll
    for (int j = 0; j < 4; ++j)
        t[ty + 8*j][tx] = in[(size_t)(r0 + ty + 8*j)*C + c0 + tx];
    __syncthreads();
#pragma unroll
    for (int j = 0; j < 4; ++j)
        out[(size_t)(c0 + ty + 8*j)*R + r0 + tx] = tf32r(t[tx][ty + 8*j]);
}

// ---------------------------------------------------------------------------
// GEMM inner machinery (ldmatrix-based), shared by qkv / outproj.
// Block tile 128x128xBK32, 8 warps (4x2), warp tile 32x64.
// ---------------------------------------------------------------------------
#define GEMM_BODY(A_LOAD_EXPR, B_LOAD_EXPR, ROUND_A)                          \
    __shared__ __align__(128) float As[4096];                                 \
    __shared__ __align__(128) float Bs[4096];                                 \
    const int tid  = threadIdx.x;                                             \
    const int warp = tid >> 5;                                                \
    const int lane = tid & 31;                                                \
    const int t    = lane & 3;  (void)t;                                      \
    const int g    = lane >> 2; (void)g;                                      \
    const int wm   = (warp >> 1) * 32;                                        \
    const int wn   = (warp & 1) * 64;                                         \
    const int f_row = tid >> 3;                                               \
    const int f_c   = tid & 7;                                                \
    const uint32_t sw = (uint32_t)(lane & 7);                                 \
    const uint32_t aSel = (uint32_t)((lane >> 4) & 1);                        \
    const uint32_t bSel = (uint32_t)((lane >> 3) & 1);                        \
    const uint32_t asm_base = smem_u32(As);                                   \
    const uint32_t bsm_base = smem_u32(Bs);                                   \
    uint32_t aBase[2], bBase[4];                                              \
    _Pragma("unroll")                                                         \
    for (int mf = 0; mf < 2; ++mf)                                            \
        aBase[mf] = asm_base + (uint32_t)(wm + mf*16 + (lane & 15)) * 128u;   \
    _Pragma("unroll")                                                         \
    for (int q = 0; q < 4; ++q)                                               \
        bBase[q] = bsm_base + (uint32_t)(wn + q*16 + ((lane>>4)&1)*8          \
                                         + (lane & 7)) * 128u;                \
    float acc[2][8][4];                                                       \
    _Pragma("unroll")                                                         \
    for (int i = 0; i < 2; ++i)                                               \
        _Pragma("unroll")                                                     \
        for (int j = 0; j < 8; ++j)                                           \
            _Pragma("unroll")                                                 \
            for (int c = 0; c < 4; ++c) acc[i][j][c] = 0.f;                   \
    float4 ar[4], br[4];                                                      \
    {   int k0 = 0;                                                           \
        _Pragma("unroll")                                                     \
        for (int p = 0; p < 4; ++p) { ar[p] = (A_LOAD_EXPR); }                \
        _Pragma("unroll")                                                     \
        for (int p = 0; p < 4; ++p) { br[p] = (B_LOAD_EXPR); }                \
    }                                                                         \
    for (int kc = 0; kc < 32; ++kc) {                                         \
        _Pragma("unroll")                                                     \
        for (int p = 0; p < 4; ++p) {                                         \
            int row = f_row + 32*p;                                           \
            float4 v = ar[p];                                                 \
            if (ROUND_A) { v.x = tf32r(v.x); v.y = tf32r(v.y);                \
                           v.z = tf32r(v.z); v.w = tf32r(v.w); }              \
            *(float4*)((char*)As + SWZ((uint32_t)(row*128 + f_c*16))) = v;    \
            *(float4*)((char*)Bs + SWZ((uint32_t)(row*128 + f_c*16))) = br[p];\
        }                                                                     \
        __syncthreads();                                                      \
        if (kc < 31) {                                                        \
            int k0 = (kc + 1) * 32;                                           \
            _Pragma("unroll")                                                 \
            for (int p = 0; p < 4; ++p) { ar[p] = (A_LOAD_EXPR); }            \
            _Pragma("unroll")                                                 \
            for (int p = 0; p < 4; ++p) { br[p] = (B_LOAD_EXPR); }            \
        }                                                                     \
        _Pragma("unroll")                                                     \
        for (int k8 = 0; k8 < 4; ++k8) {                                      \
            const uint32_t ofsA = (((uint32_t)(2*k8) + aSel) ^ sw) << 4;      \
            const uint32_t ofsB = (((uint32_t)(2*k8) + bSel) ^ sw) << 4;      \
            unsigned a0[4], a1[4];                                            \
            LDSM4(a0[0], a0[1], a0[2], a0[3], aBase[0] + ofsA);               \
            LDSM4(a1[0], a1[1], a1[2], a1[3], aBase[1] + ofsA);               \
            _Pragma("unroll")                                                 \
            for (int q = 0; q < 4; ++q) {                                     \
                unsigned b0, b1, b2, b3;                                      \
                LDSM4(b0, b1, b2, b3, bBase[q] + ofsB);                       \
                mma8(acc[0][2*q],   a0, b0, b1);                              \
                mma8(acc[1][2*q],   a1, b0, b1);                              \
                mma8(acc[0][2*q+1], a0, b2, b3);                              \
                mma8(acc[1][2*q+1], a1, b2, b3);                              \
            }                                                                 \
        }                                                                     \
        __syncthreads();                                                      \
    }

// ---------------------------------------------------------------------------
// Fused QKV projection. grid (64, 24): y -> mat (y>>3), head-pair (y&7).
// Q is written pre-scaled by 1/8; V is written transposed (B,H,E,S).
// ---------------------------------------------------------------------------
__global__ __launch_bounds__(256, 2) void qkv_kernel(
    const float* __restrict__ X,
    const float* __restrict__ bQ, const float* __restrict__ bK,
    const float* __restrict__ bV)
{
    const int m0  = blockIdx.x * 128;
    const int mat = blockIdx.y >> 3;
    const int h0  = (blockIdx.y & 7) * 2;
    const float* WT = ((mat==0) ? g_WTq : (mat==1) ? g_WTk : g_WTv)
                      + (size_t)h0 * E_ * D_;
    const float* bias = ((mat==0) ? bQ : (mat==1) ? bK : bV) + h0*E_;

    GEMM_BODY(
        (*(const float4*)(X  + (size_t)(m0 + f_row + 32*p)*D_ + k0 + f_c*4)),
        (*(const float4*)(WT + (size_t)(f_row + 32*p)*D_      + k0 + f_c*4)),
        true)

    if (mat == 2) {
        // V: transposed scatter to g_Vt (B,H,E,S)
#pragma unroll
        for (int nf = 0; nf < 8; ++nf) {
            int n = wn + nf*8 + 2*t;
            int h = n >> 6, e = n & 63;
            float bi0 = bias[h*E_ + e], bi1 = bias[h*E_ + e + 1];
#pragma unroll
            for (int mf = 0; mf < 2; ++mf) {
                int m = m0 + wm + mf*16 + g;
                int bidx = m >> 11, s = m & (S_-1);
                float* base = g_Vt + (((size_t)(bidx*H_ + h0 + h)*E_ + e)*S_) + s;
                base[0]      = acc[mf][nf][0] + bi0;
                base[8]      = acc[mf][nf][2] + bi0;
                base[S_]     = acc[mf][nf][1] + bi1;
                base[S_ + 8] = acc[mf][nf][3] + bi1;
            }
        }
    } else {
        float* out = (mat == 0) ? g_Q : g_K;
        const float scl = (mat == 0) ? 0.125f : 1.0f;
#pragma unroll
        for (int nf = 0; nf < 8; ++nf) {
            int n = wn + nf*8 + 2*t;
            int h = n >> 6, e = n & 63;
            float bi0 = bias[h*E_ + e], bi1 = bias[h*E_ + e + 1];
#pragma unroll
            for (int mf = 0; mf < 2; ++mf) {
                int m = m0 + wm + mf*16 + g;
                int bidx = m >> 11, s = m & (S_-1);
                float* r0 = out + ((size_t)(bidx*H_ + h0 + h)*S_ + s)*E_ + e;
                *(float2*)r0 = make_float2((acc[mf][nf][0] + bi0)*scl,
                                           (acc[mf][nf][1] + bi1)*scl);
                *(float2*)(r0 + 8*E_) = make_float2((acc[mf][nf][2] + bi0)*scl,
                                                    (acc[mf][nf][3] + bi1)*scl);
            }
        }
    }
}

// ---------------------------------------------------------------------------
// Output projection. grid (64, 8).
// ---------------------------------------------------------------------------
__global__ __launch_bounds__(256, 2) void outproj_kernel(
    const float* __restrict__ bO, float* __restrict__ outp)
{
    const int m0 = blockIdx.x * 128;
    const int n0 = blockIdx.y * 128;

    GEMM_BODY(
        (*(const float4*)(g_Z   + (size_t)(m0 + f_row + 32*p)*D_ + k0 + f_c*4)),
        (*(const float4*)(g_WTo + (size_t)(n0 + f_row + 32*p)*D_ + k0 + f_c*4)),
        true)

#pragma unroll
    for (int nf = 0; nf < 8; ++nf) {
        int col = n0 + wn + nf*8 + 2*t;
        float bi0 = bO[col], bi1 = bO[col+1];
#pragma unroll
        for (int mf = 0; mf < 2; ++mf) {
            int m = m0 + wm + mf*16 + g;
            *(float2*)&outp[(size_t)m*D_ + col] =
                make_float2(acc[mf][nf][0] + bi0, acc[mf][nf][1] + bi1);
            *(float2*)&outp[(size_t)(m+8)*D_ + col] =
                make_float2(acc[mf][nf][2] + bi0, acc[mf][nf][3] + bi1);
        }
    }
}

// ---------------------------------------------------------------------------
// Flash attention (causal), tf32 MMA + ldmatrix fragments.
// Block = 128 queries x (b,h). 8 warps x 16 q-rows. 64-key tiles.
// Smem: K panels 2x[64][32], Vt panels 2x[64 d][32 key], P/Q stage 8x[16][64].
// ---------------------------------------------------------------------------
#define ATT_SMEM_BYTES 65536

__global__ __launch_bounds__(256) void att_kernel()
{
    extern __shared__ char smc[];
    char* Kp  = smc;            // 2 panels x 8192
    char* Vtp = smc + 16384;    // 2 panels x 8192
    char* Pp  = smc + 32768;    // 8 warps x 4096 (2 panels x [16][32])
    const uint32_t Ku  = smem_u32(Kp);
    const uint32_t Vtu = smem_u32(Vtp);
    const uint32_t Pu  = smem_u32(Pp);

    const int tid  = threadIdx.x;
    const int warp = tid >> 5;
    const int lane = tid & 31;
    const int t    = lane & 3;
    const int g    = lane >> 2;
    const int wq   = warp * 16;
    const uint32_t sw   = (uint32_t)(lane & 7);
    const uint32_t aSel = (uint32_t)((lane >> 4) & 1);
    const uint32_t bSel = (uint32_t)((lane >> 3) & 1);

    const int qt = gridDim.x - 1 - blockIdx.x;   // big tiles first
    const int h  = blockIdx.y;
    const int b  = blockIdx.z;
    const size_t bh  = (size_t)(b*H_ + h) * S_;
    const size_t bhv = (size_t)(b*H_ + h) * E_ * S_;
    const int q0 = qt * 128;

    // ---- stage Q (pre-scaled by 1/8 in qkv) into P region, pull fragments
    {
        const float* Qb = g_Q + (bh + q0) * E_;
#pragma unroll
        for (int p = 0; p < 8; ++p) {
            int idx = tid + 256*p;
            int row = idx >> 4, c4 = idx & 15;
            float4 v = *(const float4*)(Qb + row*E_ + c4*4);
            v.x = tf32r(v.x); v.y = tf32r(v.y); v.z = tf32r(v.z); v.w = tf32r(v.w);
            *(float4*)(Pp + (row>>4)*4096 + (c4>>3)*2048
                       + SWZ((uint32_t)((row&15)*128 + (c4&7)*16))) = v;
        }
    }
    __syncthreads();
    const uint32_t pw = Pu + warp*4096;
    unsigned qf[8][4];
#pragma unroll
    for (int d8 = 0; d8 < 8; ++d8) {
        uint32_t addr = pw + (uint32_t)((d8>>2)*2048) + (uint32_t)((lane&15)*128)
                        + ((((uint32_t)(2*(d8&3)) + aSel) ^ sw) << 4);
        LDSM4(qf[d8][0], qf[d8][1], qf[d8][2], qf[d8][3], addr);
    }

    // fragment bases for K / Vt (row = n-dim: keys for K, d for Vt)
    uint32_t kB[4], vB[4];
#pragma unroll
    for (int q = 0; q < 4; ++q) {
        uint32_t r = (uint32_t)(q*16 + ((lane>>4)&1)*8 + (lane&7)) * 128u;
        kB[q] = Ku  + r;
        vB[q] = Vtu + r;
    }

    float O[8][4];
#pragma unroll
    for (int nf = 0; nf < 8; ++nf)
#pragma unroll
        for (int c = 0; c < 4; ++c) O[nf][c] = 0.f;
    float mA = -1e30f, mB = -1e30f, lA = 0.f, lB = 0.f;

    const int rowA = q0 + wq + g;
    const int rowB = rowA + 8;
    const int tmax = 2*qt + 1;

    const int l_row = tid >> 4, l_c4 = tid & 15;
    float4 kr[4], vr[4];
    auto loadKV = [&](int kt) {
        const float* Kb = g_K + (bh + kt*64) * E_;
        const float* Vb = g_Vt + bhv + kt*64;
#pragma unroll
        for (int p = 0; p < 4; ++p) {
            int row = l_row + p*16;
            kr[p] = *(const float4*)(Kb + row*E_ + l_c4*4);
            vr[p] = *(const float4*)(Vb + (size_t)row*S_ + l_c4*4);
        }
    };
    loadKV(0);

    const uint32_t fill_off = (uint32_t)((l_c4>>3)*8192);

    for (int kt = 0; kt <= tmax; ++kt) {
        __syncthreads();   // prev tile fully consumed
#pragma unroll
        for (int p = 0; p < 4; ++p) {
            int row = l_row + p*16;
            uint32_t so = fill_off + SWZ((uint32_t)(row*128 + (l_c4&7)*16));
            float4 kv = kr[p];
            kv.x = tf32r(kv.x); kv.y = tf32r(kv.y); kv.z = tf32r(kv.z); kv.w = tf32r(kv.w);
            *(float4*)(Kp + so) = kv;
            float4 vv = vr[p];
            vv.x = tf32r(vv.x); vv.y = tf32r(vv.y); vv.z = tf32r(vv.z); vv.w = tf32r(vv.w);
            *(float4*)(Vtp + so) = vv;
        }
        __syncthreads();
        if (kt < tmax) loadKV(kt+1);

        // ---- S = Q K^T (64 keys x 16 q-rows per warp), ldmatrix B
        float sv[8][4];
#pragma unroll
        for (int nf = 0; nf < 8; ++nf)
#pragma unroll
            for (int c = 0; c < 4; ++c) sv[nf][c] = 0.f;
#pragma unroll
        for (int d8 = 0; d8 < 8; ++d8) {
            uint32_t ofs = ((((uint32_t)(2*(d8&3)) + bSel) ^ sw) << 4)
                           + (uint32_t)((d8>>2)*8192);
#pragma unroll
            for (int q = 0; q < 4; ++q) {
                unsigned b0, b1, b2, b3;
                LDSM4(b0, b1, b2, b3, kB[q] + ofs);
                mma8(sv[2*q],   qf[d8], b0, b1);
                mma8(sv[2*q+1], qf[d8], b2, b3);
            }
        }

        // ---- causal mask (scale pre-folded into Q)
        const bool edge = (kt >= 2*qt);
        if (edge) {
#pragma unroll
            for (int nf = 0; nf < 8; ++nf) {
                int cb = kt*64 + nf*8 + 2*t;
                if (cb   > rowA) sv[nf][0] = -1e30f;
                if (cb+1 > rowA) sv[nf][1] = -1e30f;
                if (cb   > rowB) sv[nf][2] = -1e30f;
                if (cb+1 > rowB) sv[nf][3] = -1e30f;
            }
        }

        // ---- warp-local online softmax
        float rmA = -1e30f, rmB = -1e30f;
#pragma unroll
        for (int nf = 0; nf < 8; ++nf) {
            rmA = fmaxf(rmA, fmaxf(sv[nf][0], sv[nf][1]));
            rmB = fmaxf(rmB, fmaxf(sv[nf][2], sv[nf][3]));
        }
        rmA = fmaxf(rmA, __shfl_xor_sync(0xffffffffu, rmA, 1));
        rmA = fmaxf(rmA, __shfl_xor_sync(0xffffffffu, rmA, 2));
        rmB = fmaxf(rmB, __shfl_xor_sync(0xffffffffu, rmB, 1));
        rmB = fmaxf(rmB, __shfl_xor_sync(0xffffffffu, rmB, 2));

        float mnA = fmaxf(mA, rmA), mnB = fmaxf(mB, rmB);
        float corrA = __expf(mA - mnA), corrB = __expf(mB - mnB);
        float rsA = 0.f, rsB = 0.f;
#pragma unroll
        for (int nf = 0; nf < 8; ++nf) {
            float p0 = __expf(sv[nf][0] - mnA);
            float p1 = __expf(sv[nf][1] - mnA);
            float p2 = __expf(sv[nf][2] - mnB);
            float p3 = __expf(sv[nf][3] - mnB);
            rsA += p0 + p1; rsB += p2 + p3;
            uint32_t poff = (uint32_t)((nf>>2)*2048);
            uint32_t in0 = (uint32_t)(((nf&3)*8 + 2*t)*4);
            *(float2*)((char*)Pp + (pw - Pu) + poff
                       + SWZ((uint32_t)(g*128) + in0)) =
                make_float2(tf32r(p0), tf32r(p1));
            *(float2*)((char*)Pp + (pw - Pu) + poff
                       + SWZ((uint32_t)((g+8)*128) + in0)) =
                make_float2(tf32r(p2), tf32r(p3));
        }
        rsA += __shfl_xor_sync(0xffffffffu, rsA, 1);
        rsA += __shfl_xor_sync(0xffffffffu, rsA, 2);
        rsB += __shfl_xor_sync(0xffffffffu, rsB, 1);
        rsB += __shfl_xor_sync(0xffffffffu, rsB, 2);
        lA = lA*corrA + rsA; mA = mnA;
        lB = lB*corrB + rsB; mB = mnB;
#pragma unroll
        for (int nf = 0; nf < 8; ++nf) {
            O[nf][0] *= corrA; O[nf][1] *= corrA;
            O[nf][2] *= corrB; O[nf][3] *= corrB;
        }
        __syncwarp();

        // ---- O += P V   (ldmatrix A from P stage, B from Vt panels)
#pragma unroll
        for (int kk = 0; kk < 8; ++kk) {
            uint32_t pofs = pw + (uint32_t)((kk>>2)*2048)
                            + (uint32_t)((lane&15)*128)
                            + ((((uint32_t)(2*(kk&3)) + aSel) ^ sw) << 4);
            unsigned pa[4];
            LDSM4(pa[0], pa[1], pa[2], pa[3], pofs);
            uint32_t ofs = ((((uint32_t)(2*(kk&3)) + bSel) ^ sw) << 4)
                           + (uint32_t)((kk>>2)*8192);
#pragma unroll
            for (int q = 0; q < 4; ++q) {
                unsigned b0, b1, b2, b3;
                LDSM4(b0, b1, b2, b3, vB[q] + ofs);
                mma8(O[2*q],   pa, b0, b1);
                mma8(O[2*q+1], pa, b2, b3);
            }
        }
    }

    // ---- epilogue: normalize + write z (B,S,H*E)
    float invA = 1.0f / lA, invB = 1.0f / lB;
    float* zA = g_Z + (size_t)(b*S_ + q0 + wq + g    )*(H_*E_) + h*E_;
    float* zB = g_Z + (size_t)(b*S_ + q0 + wq + g + 8)*(H_*E_) + h*E_;
#pragma unroll
    for (int nf = 0; nf < 8; ++nf) {
        int col = nf*8 + 2*t;
        *(float2*)(zA + col) = make_float2(O[nf][0]*invA, O[nf][1]*invA);
        *(float2*)(zB + col) = make_float2(O[nf][2]*invB, O[nf][3]*invB);
    }
}

// ---------------------------------------------------------------------------
extern "C" void kernel_launch(void* const* d_in, const int* in_sizes, int n_in,
                              void* d_out, int out_size)
{
    const float* x   = (const float*)d_in[0];
    const float* W_Q = (const float*)d_in[1];
    const float* b_Q = (const float*)d_in[2];
    const float* W_K = (const float*)d_in[3];
    const float* b_K = (const float*)d_in[4];
    const float* W_V = (const float*)d_in[5];
    const float* b_V = (const float*)d_in[6];
    const float* W_O = (const float*)d_in[7];
    const float* b_O = (const float*)d_in[8];
    float* out = (float*)d_out;

    cudaFuncSetAttribute(att_kernel,
        cudaFuncAttributeMaxDynamicSharedMemorySize, ATT_SMEM_BYTES);

    float *wtq, *wtk, *wtv, *wto;
    cudaGetSymbolAddress((void**)&wtq, g_WTq);
    cudaGetSymbolAddress((void**)&wtk, g_WTk);
    cudaGetSymbolAddress((void**)&wtv, g_WTv);
    cudaGetSymbolAddress((void**)&wto, g_WTo);

    dim3 tb(32, 8);
    transpose_rc<<<dim3(32, 2, 16), tb>>>(W_Q, wtq, D_, E_);
    transpose_rc<<<dim3(32, 2, 16), tb>>>(W_K, wtk, D_, E_);
    transpose_rc<<<dim3(32, 2, 16), tb>>>(W_V, wtv, D_, E_);
    transpose_rc<<<dim3(32, 32, 1), tb>>>(W_O, wto, D_, D_);

    dim3 gqkv(M_/128, 24);
    qkv_kernel<<<gqkv, 256>>>(x, b_Q, b_K, b_V);

    dim3 gatt(S_/128, H_, B_);
    att_kernel<<<gatt, 256, ATT_SMEM_BYTES>>>();

    dim3 gout(M_/128, D_/128);
    outproj_kernel<<<gout, 256>>>(b_O, out);
}

// round 14
// speedup vs baseline: 3.6331x; 1.0974x over previous
#include <cuda_runtime.h>
#include <cuda_bf16.h>
#include <cstdint>

#define B_ 4
#define S_ 2048
#define D_ 1024
#define H_ 16
#define E_ 64
#define M_ (B_*S_)   // 8192

// Scratch (allocation-free rule: __device__ globals)
__device__ float g_Q [(size_t)B_*H_*S_*E_];  // (B,H,S,E) pre-scaled 0.125*log2e, tf32-rounded
__device__ float g_K [(size_t)B_*H_*S_*E_];  // (B,H,S,E) tf32-rounded
__device__ float g_Vt[(size_t)B_*H_*E_*S_];  // (B,H,E,S) V transposed, tf32-rounded
__device__ float g_Z [(size_t)B_*S_*H_*E_];  // (B,S,H*E)
// Pre-transposed (and tf32-rounded) weights: [h][e][k] / [n][k]
__device__ float g_WTq[(size_t)H_*E_*D_];
__device__ float g_WTk[(size_t)H_*E_*D_];
__device__ float g_WTv[(size_t)H_*E_*D_];
__device__ float g_WTo[(size_t)D_*D_];

#define QSCL 0.1803368801111204f   // 0.125 * log2(e)

// ---------------------------------------------------------------------------
// Helpers
// ---------------------------------------------------------------------------
__device__ __forceinline__ float tf32r(float x) {
    asm("cvt.rna.tf32.f32 %0, %1;" : "=f"(x) : "f"(x));
    return x;
}
__device__ __forceinline__ unsigned fu(float x) { return __float_as_uint(x); }

__device__ __forceinline__ void mma8(float* d, const unsigned* a,
                                     unsigned b0, unsigned b1) {
    asm volatile(
        "mma.sync.aligned.m16n8k8.row.col.f32.tf32.tf32.f32 "
        "{%0,%1,%2,%3}, {%4,%5,%6,%7}, {%8,%9}, {%0,%1,%2,%3};\n"
        : "+f"(d[0]), "+f"(d[1]), "+f"(d[2]), "+f"(d[3])
        : "r"(a[0]), "r"(a[1]), "r"(a[2]), "r"(a[3]), "r"(b0), "r"(b1));
}

__device__ __forceinline__ uint32_t smem_u32(const void* p) {
    uint32_t a;
    asm("{ .reg .u64 t; cvta.to.shared.u64 t, %1; cvt.u32.u64 %0, t; }"
        : "=r"(a) : "l"(p));
    return a;
}

#define LDSM4(r0, r1, r2, r3, addr) \
    asm volatile("ldmatrix.sync.aligned.m8n8.x4.shared.b16 {%0,%1,%2,%3}, [%4];" \
        : "=r"(r0), "=r"(r1), "=r"(r2), "=r"(r3) : "r"(addr))

#define CP16(dst, src) \
    asm volatile("cp.async.cg.shared.global [%0], [%1], 16;" \
        :: "r"(dst), "l"(src) : "memory")
#define CP_COMMIT() asm volatile("cp.async.commit_group;" ::: "memory")
#define CP_WAIT0()  asm volatile("cp.async.wait_group 0;" ::: "memory")

// SW128 swizzle on byte offsets (rows of 128B)
#define SWZ(x) ((x) ^ (((x) >> 3) & 0x70))

// ---------------------------------------------------------------------------
// Weight transpose + tf32 rounding: out[z][c][r] = round(in[z][r][c])
// ---------------------------------------------------------------------------
__global__ void transpose_rc(const float* __restrict__ in, float* __restrict__ out,
                             int R, int C)
{
    __shared__ float t[32][33];
    const size_t zo = (size_t)blockIdx.z * R * C;
    in  += zo; out += zo;
    int r0 = blockIdx.x*32, c0 = blockIdx.y*32;
    int tx = threadIdx.x, ty = threadIdx.y;
#pragma unroll
    for (int j = 0; j < 4; ++j)
        t[ty + 8*j][tx] = in[(size_t)(r0 + ty + 8*j)*C + c0 + tx];
    __syncthreads();
#pragma unroll
    for (int j = 0; j < 4; ++j)
        out[(size_t)(c0 + ty + 8*j)*R + r0 + tx] = tf32r(t[tx][ty + 8*j]);
}

// ---------------------------------------------------------------------------
// GEMM inner machinery (ldmatrix-based), shared by qkv / outproj.
// Block tile 128x128xBK32, 8 warps (4x2), warp tile 32x64.
// ---------------------------------------------------------------------------
#define GEMM_BODY(A_LOAD_EXPR, B_LOAD_EXPR, ROUND_A)                          \
    __shared__ __align__(128) float As[4096];                                 \
    __shared__ __align__(128) float Bs[4096];                                 \
    const int tid  = threadIdx.x;                                             \
    const int warp = tid >> 5;                                                \
    const int lane = tid & 31;                                                \
    const int t    = lane & 3;  (void)t;                                      \
    const int g    = lane >> 2; (void)g;                                      \
    const int wm   = (warp >> 1) * 32;                                        \
    const int wn   = (warp & 1) * 64;                                         \
    const int f_row = tid >> 3;                                               \
    const int f_c   = tid & 7;                                                \
    const uint32_t sw = (uint32_t)(lane & 7);                                 \
    const uint32_t aSel = (uint32_t)((lane >> 4) & 1);                        \
    const uint32_t bSel = (uint32_t)((lane >> 3) & 1);                        \
    const uint32_t asm_base = smem_u32(As);                                   \
    const uint32_t bsm_base = smem_u32(Bs);                                   \
    uint32_t aBase[2], bBase[4];                                              \
    _Pragma("unroll")                                                         \
    for (int mf = 0; mf < 2; ++mf)                                            \
        aBase[mf] = asm_base + (uint32_t)(wm + mf*16 + (lane & 15)) * 128u;   \
    _Pragma("unroll")                                                         \
    for (int q = 0; q < 4; ++q)                                               \
        bBase[q] = bsm_base + (uint32_t)(wn + q*16 + ((lane>>4)&1)*8          \
                                         + (lane & 7)) * 128u;                \
    float acc[2][8][4];                                                       \
    _Pragma("unroll")                                                         \
    for (int i = 0; i < 2; ++i)                                               \
        _Pragma("unroll")                                                     \
        for (int j = 0; j < 8; ++j)                                           \
            _Pragma("unroll")                                                 \
            for (int c = 0; c < 4; ++c) acc[i][j][c] = 0.f;                   \
    float4 ar[4], br[4];                                                      \
    {   int k0 = 0;                                                           \
        _Pragma("unroll")                                                     \
        for (int p = 0; p < 4; ++p) { ar[p] = (A_LOAD_EXPR); }                \
        _Pragma("unroll")                                                     \
        for (int p = 0; p < 4; ++p) { br[p] = (B_LOAD_EXPR); }                \
    }                                                                         \
    for (int kc = 0; kc < 32; ++kc) {                                         \
        _Pragma("unroll")                                                     \
        for (int p = 0; p < 4; ++p) {                                         \
            int row = f_row + 32*p;                                           \
            float4 v = ar[p];                                                 \
            if (ROUND_A) { v.x = tf32r(v.x); v.y = tf32r(v.y);                \
                           v.z = tf32r(v.z); v.w = tf32r(v.w); }              \
            *(float4*)((char*)As + SWZ((uint32_t)(row*128 + f_c*16))) = v;    \
            *(float4*)((char*)Bs + SWZ((uint32_t)(row*128 + f_c*16))) = br[p];\
        }                                                                     \
        __syncthreads();                                                      \
        if (kc < 31) {                                                        \
            int k0 = (kc + 1) * 32;                                           \
            _Pragma("unroll")                                                 \
            for (int p = 0; p < 4; ++p) { ar[p] = (A_LOAD_EXPR); }            \
            _Pragma("unroll")                                                 \
            for (int p = 0; p < 4; ++p) { br[p] = (B_LOAD_EXPR); }            \
        }                                                                     \
        _Pragma("unroll")                                                     \
        for (int k8 = 0; k8 < 4; ++k8) {                                      \
            const uint32_t ofsA = (((uint32_t)(2*k8) + aSel) ^ sw) << 4;      \
            const uint32_t ofsB = (((uint32_t)(2*k8) + bSel) ^ sw) << 4;      \
            unsigned a0[4], a1[4];                                            \
            LDSM4(a0[0], a0[1], a0[2], a0[3], aBase[0] + ofsA);               \
            LDSM4(a1[0], a1[1], a1[2], a1[3], aBase[1] + ofsA);               \
            _Pragma("unroll")                                                 \
            for (int q = 0; q < 4; ++q) {                                     \
                unsigned b0, b1, b2, b3;                                      \
                LDSM4(b0, b1, b2, b3, bBase[q] + ofsB);                       \
                mma8(acc[0][2*q],   a0, b0, b1);                              \
                mma8(acc[1][2*q],   a1, b0, b1);                              \
                mma8(acc[0][2*q+1], a0, b2, b3);                              \
                mma8(acc[1][2*q+1], a1, b2, b3);                              \
            }                                                                 \
        }                                                                     \
        __syncthreads();                                                      \
    }

// ---------------------------------------------------------------------------
// Fused QKV projection. grid (64, 24): y -> mat (y>>3), head-pair (y&7).
// Q: pre-scaled by 0.125*log2e + tf32-rounded. K: tf32-rounded.
// V: transposed (B,H,E,S) + tf32-rounded.
// ---------------------------------------------------------------------------
__global__ __launch_bounds__(256, 2) void qkv_kernel(
    const float* __restrict__ X,
    const float* __restrict__ bQ, const float* __restrict__ bK,
    const float* __restrict__ bV)
{
    const int m0  = blockIdx.x * 128;
    const int mat = blockIdx.y >> 3;
    const int h0  = (blockIdx.y & 7) * 2;
    const float* WT = ((mat==0) ? g_WTq : (mat==1) ? g_WTk : g_WTv)
                      + (size_t)h0 * E_ * D_;
    const float* bias = ((mat==0) ? bQ : (mat==1) ? bK : bV) + h0*E_;

    GEMM_BODY(
        (*(const float4*)(X  + (size_t)(m0 + f_row + 32*p)*D_ + k0 + f_c*4)),
        (*(const float4*)(WT + (size_t)(f_row + 32*p)*D_      + k0 + f_c*4)),
        true)

    if (mat == 2) {
        // V: transposed scatter to g_Vt (B,H,E,S), tf32-rounded
#pragma unroll
        for (int nf = 0; nf < 8; ++nf) {
            int n = wn + nf*8 + 2*t;
            int h = n >> 6, e = n & 63;
            float bi0 = bias[h*E_ + e], bi1 = bias[h*E_ + e + 1];
#pragma unroll
            for (int mf = 0; mf < 2; ++mf) {
                int m = m0 + wm + mf*16 + g;
                int bidx = m >> 11, s = m & (S_-1);
                float* base = g_Vt + (((size_t)(bidx*H_ + h0 + h)*E_ + e)*S_) + s;
                base[0]      = tf32r(acc[mf][nf][0] + bi0);
                base[8]      = tf32r(acc[mf][nf][2] + bi0);
                base[S_]     = tf32r(acc[mf][nf][1] + bi1);
                base[S_ + 8] = tf32r(acc[mf][nf][3] + bi1);
            }
        }
    } else {
        float* out = (mat == 0) ? g_Q : g_K;
        const float scl = (mat == 0) ? QSCL : 1.0f;
#pragma unroll
        for (int nf = 0; nf < 8; ++nf) {
            int n = wn + nf*8 + 2*t;
            int h = n >> 6, e = n & 63;
            float bi0 = bias[h*E_ + e], bi1 = bias[h*E_ + e + 1];
#pragma unroll
            for (int mf = 0; mf < 2; ++mf) {
                int m = m0 + wm + mf*16 + g;
                int bidx = m >> 11, s = m & (S_-1);
                float* r0 = out + ((size_t)(bidx*H_ + h0 + h)*S_ + s)*E_ + e;
                *(float2*)r0 = make_float2(tf32r((acc[mf][nf][0] + bi0)*scl),
                                           tf32r((acc[mf][nf][1] + bi1)*scl));
                *(float2*)(r0 + 8*E_) = make_float2(tf32r((acc[mf][nf][2] + bi0)*scl),
                                                    tf32r((acc[mf][nf][3] + bi1)*scl));
            }
        }
    }
}

// ---------------------------------------------------------------------------
// Output projection. grid (64, 8).
// ---------------------------------------------------------------------------
__global__ __launch_bounds__(256, 2) void outproj_kernel(
    const float* __restrict__ bO, float* __restrict__ outp)
{
    const int m0 = blockIdx.x * 128;
    const int n0 = blockIdx.y * 128;

    GEMM_BODY(
        (*(const float4*)(g_Z   + (size_t)(m0 + f_row + 32*p)*D_ + k0 + f_c*4)),
        (*(const float4*)(g_WTo + (size_t)(n0 + f_row + 32*p)*D_ + k0 + f_c*4)),
        true)

#pragma unroll
    for (int nf = 0; nf < 8; ++nf) {
        int col = n0 + wn + nf*8 + 2*t;
        float bi0 = bO[col], bi1 = bO[col+1];
#pragma unroll
        for (int mf = 0; mf < 2; ++mf) {
            int m = m0 + wm + mf*16 + g;
            *(float2*)&outp[(size_t)m*D_ + col] =
                make_float2(acc[mf][nf][0] + bi0, acc[mf][nf][1] + bi1);
            *(float2*)&outp[(size_t)(m+8)*D_ + col] =
                make_float2(acc[mf][nf][2] + bi0, acc[mf][nf][3] + bi1);
        }
    }
}

// ---------------------------------------------------------------------------
// Flash attention (causal), tf32 MMA + ldmatrix + cp.async double buffering.
// Block = 128 queries x (b,h), 8 warps x 16 q-rows, 64-key tiles.
// Smem: K 2x16KB, Vt 2x16KB, P/Q stage 8x4KB = 96KB -> 2 CTAs/SM.
// ---------------------------------------------------------------------------
#define ATT_SMEM_BYTES 98304

__global__ __launch_bounds__(256, 2) void att_kernel()
{
    extern __shared__ char smc[];
    char* Pp  = smc + 65536;    // 8 warps x 4096
    const uint32_t Ku  = smem_u32(smc);            // 2 bufs x 16384
    const uint32_t Vtu = Ku + 32768;               // 2 bufs x 16384
    const uint32_t Pu  = Ku + 65536;

    const int tid  = threadIdx.x;
    const int warp = tid >> 5;
    const int lane = tid & 31;
    const int t    = lane & 3;
    const int g    = lane >> 2;
    const int wq   = warp * 16;
    const uint32_t sw   = (uint32_t)(lane & 7);
    const uint32_t aSel = (uint32_t)((lane >> 4) & 1);
    const uint32_t bSel = (uint32_t)((lane >> 3) & 1);

    const int qt = gridDim.x - 1 - blockIdx.x;   // big tiles first
    const int h  = blockIdx.y;
    const int b  = blockIdx.z;
    const size_t bh  = (size_t)(b*H_ + h) * S_;
    const size_t bhv = (size_t)(b*H_ + h) * E_ * S_;
    const int q0 = qt * 128;

    const int l_row = tid >> 4, l_c4 = tid & 15;
    const uint32_t fill_off = (uint32_t)((l_c4>>3)*8192);

    // ---- kick off cp.async fill of K/Vt tile 0 into buffer 0
    auto cpFill = [&](int bbuf, int kt) {
        const float* Kb = g_K + (bh + kt*64) * E_;
        const float* Vb = g_Vt + bhv + kt*64;
        const uint32_t bo = (uint32_t)(bbuf*16384) + fill_off;
#pragma unroll
        for (int p = 0; p < 4; ++p) {
            int row = l_row + p*16;
            uint32_t so = bo + SWZ((uint32_t)(row*128 + (l_c4&7)*16));
            CP16(Ku  + so, Kb + row*E_ + l_c4*4);
            CP16(Vtu + so, Vb + (size_t)row*S_ + l_c4*4);
        }
        CP_COMMIT();
    };
    cpFill(0, 0);

    // ---- stage Q (pre-scaled/rounded) into P region, pull fragments
    {
        const float* Qb = g_Q + (bh + q0) * E_;
#pragma unroll
        for (int p = 0; p < 8; ++p) {
            int idx = tid + 256*p;
            int row = idx >> 4, c4 = idx & 15;
            float4 v = *(const float4*)(Qb + row*E_ + c4*4);
            *(float4*)(Pp + (row>>4)*4096 + (c4>>3)*2048
                       + SWZ((uint32_t)((row&15)*128 + (c4&7)*16))) = v;
        }
    }
    __syncthreads();
    const uint32_t pw = Pu + warp*4096;
    unsigned qf[8][4];
#pragma unroll
    for (int d8 = 0; d8 < 8; ++d8) {
        uint32_t addr = pw + (uint32_t)((d8>>2)*2048) + (uint32_t)((lane&15)*128)
                        + ((((uint32_t)(2*(d8&3)) + aSel) ^ sw) << 4);
        LDSM4(qf[d8][0], qf[d8][1], qf[d8][2], qf[d8][3], addr);
    }

    // fragment bases for K / Vt (buffer 0; add 16384*bb at use)
    uint32_t kB[4], vB[4];
#pragma unroll
    for (int q = 0; q < 4; ++q) {
        uint32_t r = (uint32_t)(q*16 + ((lane>>4)&1)*8 + (lane&7)) * 128u;
        kB[q] = Ku  + r;
        vB[q] = Vtu + r;
    }

    float O[8][4];
#pragma unroll
    for (int nf = 0; nf < 8; ++nf)
#pragma unroll
        for (int c = 0; c < 4; ++c) O[nf][c] = 0.f;
    float mA = -1e30f, mB = -1e30f, lA = 0.f, lB = 0.f;

    const int rowA = q0 + wq + g;
    const int rowB = rowA + 8;
    const int tmax = 2*qt + 1;
    int bb = 0;

    for (int kt = 0; kt <= tmax; ++kt) {
        CP_WAIT0();
        __syncthreads();   // buffer bb data visible to all; prev compute done
        if (kt < tmax) cpFill(bb ^ 1, kt + 1);
        const uint32_t bo = (uint32_t)(bb * 16384);

        // ---- S = Q K^T (64 keys x 16 q-rows per warp), ldmatrix B
        float sv[8][4];
#pragma unroll
        for (int nf = 0; nf < 8; ++nf)
#pragma unroll
            for (int c = 0; c < 4; ++c) sv[nf][c] = 0.f;
#pragma unroll
        for (int d8 = 0; d8 < 8; ++d8) {
            uint32_t ofs = bo + ((((uint32_t)(2*(d8&3)) + bSel) ^ sw) << 4)
                           + (uint32_t)((d8>>2)*8192);
#pragma unroll
            for (int q = 0; q < 4; ++q) {
                unsigned b0, b1, b2, b3;
                LDSM4(b0, b1, b2, b3, kB[q] + ofs);
                mma8(sv[2*q],   qf[d8], b0, b1);
                mma8(sv[2*q+1], qf[d8], b2, b3);
            }
        }

        // ---- causal mask (scale+log2e pre-folded into Q)
        const bool edge = (kt >= 2*qt);
        if (edge) {
#pragma unroll
            for (int nf = 0; nf < 8; ++nf) {
                int cb = kt*64 + nf*8 + 2*t;
                if (cb   > rowA) sv[nf][0] = -1e30f;
                if (cb+1 > rowA) sv[nf][1] = -1e30f;
                if (cb   > rowB) sv[nf][2] = -1e30f;
                if (cb+1 > rowB) sv[nf][3] = -1e30f;
            }
        }

        // ---- warp-local online softmax (base-2)
        float rmA = -1e30f, rmB = -1e30f;
#pragma unroll
        for (int nf = 0; nf < 8; ++nf) {
            rmA = fmaxf(rmA, fmaxf(sv[nf][0], sv[nf][1]));
            rmB = fmaxf(rmB, fmaxf(sv[nf][2], sv[nf][3]));
        }
        rmA = fmaxf(rmA, __shfl_xor_sync(0xffffffffu, rmA, 1));
        rmA = fmaxf(rmA, __shfl_xor_sync(0xffffffffu, rmA, 2));
        rmB = fmaxf(rmB, __shfl_xor_sync(0xffffffffu, rmB, 1));
        rmB = fmaxf(rmB, __shfl_xor_sync(0xffffffffu, rmB, 2));

        float mnA = fmaxf(mA, rmA), mnB = fmaxf(mB, rmB);
        float corrA = exp2f(mA - mnA), corrB = exp2f(mB - mnB);
        float rsA = 0.f, rsB = 0.f;
#pragma unroll
        for (int nf = 0; nf < 8; ++nf) {
            float p0 = exp2f(sv[nf][0] - mnA);
            float p1 = exp2f(sv[nf][1] - mnA);
            float p2 = exp2f(sv[nf][2] - mnB);
            float p3 = exp2f(sv[nf][3] - mnB);
            rsA += p0 + p1; rsB += p2 + p3;
            uint32_t poff = (uint32_t)((nf>>2)*2048);
            uint32_t in0 = (uint32_t)(((nf&3)*8 + 2*t)*4);
            *(float2*)((char*)Pp + (pw - Pu) + poff
                       + SWZ((uint32_t)(g*128) + in0)) =
                make_float2(tf32r(p0), tf32r(p1));
            *(float2*)((char*)Pp + (pw - Pu) + poff
                       + SWZ((uint32_t)((g+8)*128) + in0)) =
                make_float2(tf32r(p2), tf32r(p3));
        }
        rsA += __shfl_xor_sync(0xffffffffu, rsA, 1);
        rsA += __shfl_xor_sync(0xffffffffu, rsA, 2);
        rsB += __shfl_xor_sync(0xffffffffu, rsB, 1);
        rsB += __shfl_xor_sync(0xffffffffu, rsB, 2);
        lA = lA*corrA + rsA; mA = mnA;
        lB = lB*corrB + rsB; mB = mnB;
#pragma unroll
        for (int nf = 0; nf < 8; ++nf) {
            O[nf][0] *= corrA; O[nf][1] *= corrA;
            O[nf][2] *= corrB; O[nf][3] *= corrB;
        }
        __syncwarp();

        // ---- O += P V   (ldmatrix A from P stage, B from Vt panels)
#pragma unroll
        for (int kk = 0; kk < 8; ++kk) {
            uint32_t pofs = pw + (uint32_t)((kk>>2)*2048)
                            + (uint32_t)((lane&15)*128)
                            + ((((uint32_t)(2*(kk&3)) + aSel) ^ sw) << 4);
            unsigned pa[4];
            LDSM4(pa[0], pa[1], pa[2], pa[3], pofs);
            uint32_t ofs = bo + ((((uint32_t)(2*(kk&3)) + bSel) ^ sw) << 4)
                           + (uint32_t)((kk>>2)*8192);
#pragma unroll
            for (int q = 0; q < 4; ++q) {
                unsigned b0, b1, b2, b3;
                LDSM4(b0, b1, b2, b3, vB[q] + ofs);
                mma8(O[2*q],   pa, b0, b1);
                mma8(O[2*q+1], pa, b2, b3);
            }
        }
        bb ^= 1;
    }

    // ---- epilogue: normalize + write z (B,S,H*E)
    float invA = 1.0f / lA, invB = 1.0f / lB;
    float* zA = g_Z + (size_t)(b*S_ + q0 + wq + g    )*(H_*E_) + h*E_;
    float* zB = g_Z + (size_t)(b*S_ + q0 + wq + g + 8)*(H_*E_) + h*E_;
#pragma unroll
    for (int nf = 0; nf < 8; ++nf) {
        int col = nf*8 + 2*t;
        *(float2*)(zA + col) = make_float2(O[nf][0]*invA, O[nf][1]*invA);
        *(float2*)(zB + col) = make_float2(O[nf][2]*invB, O[nf][3]*invB);
    }
}

// ---------------------------------------------------------------------------
extern "C" void kernel_launch(void* const* d_in, const int* in_sizes, int n_in,
                              void* d_out, int out_size)
{
    const float* x   = (const float*)d_in[0];
    const float* W_Q = (const float*)d_in[1];
    const float* b_Q = (const float*)d_in[2];
    const float* W_K = (const float*)d_in[3];
    const float* b_K = (const float*)d_in[4];
    const float* W_V = (const float*)d_in[5];
    const float* b_V = (const float*)d_in[6];
    const float* W_O = (const float*)d_in[7];
    const float* b_O = (const float*)d_in[8];
    float* out = (float*)d_out;

    cudaFuncSetAttribute(att_kernel,
        cudaFuncAttributeMaxDynamicSharedMemorySize, ATT_SMEM_BYTES);

    float *wtq, *wtk, *wtv, *wto;
    cudaGetSymbolAddress((void**)&wtq, g_WTq);
    cudaGetSymbolAddress((void**)&wtk, g_WTk);
    cudaGetSymbolAddress((void**)&wtv, g_WTv);
    cudaGetSymbolAddress((void**)&wto, g_WTo);

    dim3 tb(32, 8);
    transpose_rc<<<dim3(32, 2, 16), tb>>>(W_Q, wtq, D_, E_);
    transpose_rc<<<dim3(32, 2, 16), tb>>>(W_K, wtk, D_, E_);
    transpose_rc<<<dim3(32, 2, 16), tb>>>(W_V, wtv, D_, E_);
    transpose_rc<<<dim3(32, 32, 1), tb>>>(W_O, wto, D_, D_);

    dim3 gqkv(M_/128, 24);
    qkv_kernel<<<gqkv, 256>>>(x, b_Q, b_K, b_V);

    dim3 gatt(S_/128, H_, B_);
    att_kernel<<<gatt, 256, ATT_SMEM_BYTES>>>();

    dim3 gout(M_/128, D_/128);
    outproj_kernel<<<gout, 256>>>(b_O, out);
}

// round 15
// speedup vs baseline: 4.2645x; 1.1738x over previous
#include <cuda_runtime.h>
#include <cuda_bf16.h>
#include <cstdint>

#define B_ 4
#define S_ 2048
#define D_ 1024
#define H_ 16
#define E_ 64
#define M_ (B_*S_)   // 8192

// Scratch (allocation-free rule: __device__ globals)
__device__ float g_Q [(size_t)B_*H_*S_*E_];  // (B,H,S,E) pre-scaled 0.125*log2e, tf32-rounded
__device__ float g_K [(size_t)B_*H_*S_*E_];  // (B,H,S,E) tf32-rounded
__device__ float g_Vt[(size_t)B_*H_*E_*S_];  // (B,H,E,S) V transposed, tf32-rounded
__device__ float g_Z [(size_t)B_*S_*H_*E_];  // (B,S,H*E) tf32-rounded (att epilogue)
__device__ float g_Xr[(size_t)M_*D_];        // tf32-rounded x
// Pre-transposed (and tf32-rounded) weights: [h][e][k] / [n][k]
__device__ float g_WTq[(size_t)H_*E_*D_];
__device__ float g_WTk[(size_t)H_*E_*D_];
__device__ float g_WTv[(size_t)H_*E_*D_];
__device__ float g_WTo[(size_t)D_*D_];

#define QSCL 0.1803368801111204f   // 0.125 * log2(e)

// ---------------------------------------------------------------------------
// Helpers
// ---------------------------------------------------------------------------
__device__ __forceinline__ float tf32r(float x) {
    asm("cvt.rna.tf32.f32 %0, %1;" : "=f"(x) : "f"(x));
    return x;
}
__device__ __forceinline__ unsigned fu(float x) { return __float_as_uint(x); }

__device__ __forceinline__ void mma8(float* d, const unsigned* a,
                                     unsigned b0, unsigned b1) {
    asm volatile(
        "mma.sync.aligned.m16n8k8.row.col.f32.tf32.tf32.f32 "
        "{%0,%1,%2,%3}, {%4,%5,%6,%7}, {%8,%9}, {%0,%1,%2,%3};\n"
        : "+f"(d[0]), "+f"(d[1]), "+f"(d[2]), "+f"(d[3])
        : "r"(a[0]), "r"(a[1]), "r"(a[2]), "r"(a[3]), "r"(b0), "r"(b1));
}

__device__ __forceinline__ uint32_t smem_u32(const void* p) {
    uint32_t a;
    asm("{ .reg .u64 t; cvta.to.shared.u64 t, %1; cvt.u32.u64 %0, t; }"
        : "=r"(a) : "l"(p));
    return a;
}

#define LDSM4(r0, r1, r2, r3, addr) \
    asm volatile("ldmatrix.sync.aligned.m8n8.x4.shared.b16 {%0,%1,%2,%3}, [%4];" \
        : "=r"(r0), "=r"(r1), "=r"(r2), "=r"(r3) : "r"(addr))

#define CP16(dst, src) \
    asm volatile("cp.async.cg.shared.global [%0], [%1], 16;" \
        :: "r"(dst), "l"(src) : "memory")
#define CP_COMMIT() asm volatile("cp.async.commit_group;" ::: "memory")
#define CP_WAIT0()  asm volatile("cp.async.wait_group 0;" ::: "memory")

// SW128 swizzle on byte offsets (rows of 128B)
#define SWZ(x) ((x) ^ (((x) >> 3) & 0x70))

// ---------------------------------------------------------------------------
// Elementwise tf32 rounding of x (once per launch)
// ---------------------------------------------------------------------------
__global__ void round_x(const float* __restrict__ in)
{
    int i = blockIdx.x * blockDim.x + threadIdx.x;
    float4 v = ((const float4*)in)[i];
    v.x = tf32r(v.x); v.y = tf32r(v.y); v.z = tf32r(v.z); v.w = tf32r(v.w);
    ((float4*)g_Xr)[i] = v;
}

// ---------------------------------------------------------------------------
// Weight transpose + tf32 rounding: out[z][c][r] = round(in[z][r][c])
// ---------------------------------------------------------------------------
__global__ void transpose_rc(const float* __restrict__ in, float* __restrict__ out,
                             int R, int C)
{
    __shared__ float t[32][33];
    const size_t zo = (size_t)blockIdx.z * R * C;
    in  += zo; out += zo;
    int r0 = blockIdx.x*32, c0 = blockIdx.y*32;
    int tx = threadIdx.x, ty = threadIdx.y;
#pragma unroll
    for (int j = 0; j < 4; ++j)
        t[ty + 8*j][tx] = in[(size_t)(r0 + ty + 8*j)*C + c0 + tx];
    __syncthreads();
#pragma unroll
    for (int j = 0; j < 4; ++j)
        out[(size_t)(c0 + ty + 8*j)*R + r0 + tx] = tf32r(t[tx][ty + 8*j]);
}

// ---------------------------------------------------------------------------
// GEMM inner machinery: cp.async double-buffered, ldmatrix fragments.
// Block tile 128x128xBK32, 8 warps (4x2), warp tile 32x64.
// Dynamic smem: 2 buffers x (As 16KB + Bs 16KB) = 64KB. Operands pre-rounded.
// A_PTR_EXPR / B_PTR_EXPR: const float* for (row = f_row+32*p, k0, 16B chunk f_c).
// ---------------------------------------------------------------------------
#define GEMM_SMEM_BYTES 65536

#define GEMM_BODY(A_PTR_EXPR, B_PTR_EXPR)                                     \
    extern __shared__ char gsm[];                                             \
    const int tid  = threadIdx.x;                                             \
    const int warp = tid >> 5;                                                \
    const int lane = tid & 31;                                                \
    const int t    = lane & 3;  (void)t;                                      \
    const int g    = lane >> 2; (void)g;                                      \
    const int wm   = (warp >> 1) * 32;                                        \
    const int wn   = (warp & 1) * 64;                                         \
    const int f_row = tid >> 3;                                               \
    const int f_c   = tid & 7;                                                \
    const uint32_t sw = (uint32_t)(lane & 7);                                 \
    const uint32_t aSel = (uint32_t)((lane >> 4) & 1);                        \
    const uint32_t bSel = (uint32_t)((lane >> 3) & 1);                        \
    const uint32_t smb = smem_u32(gsm);                                       \
    uint32_t aBase[2], bBase[4];                                              \
    _Pragma("unroll")                                                         \
    for (int mf = 0; mf < 2; ++mf)                                            \
        aBase[mf] = smb + (uint32_t)(wm + mf*16 + (lane & 15)) * 128u;        \
    _Pragma("unroll")                                                         \
    for (int q = 0; q < 4; ++q)                                               \
        bBase[q] = smb + 16384u + (uint32_t)(wn + q*16 + ((lane>>4)&1)*8      \
                                             + (lane & 7)) * 128u;            \
    float acc[2][8][4];                                                       \
    _Pragma("unroll")                                                         \
    for (int i = 0; i < 2; ++i)                                               \
        _Pragma("unroll")                                                     \
        for (int j = 0; j < 8; ++j)                                           \
            _Pragma("unroll")                                                 \
            for (int c = 0; c < 4; ++c) acc[i][j][c] = 0.f;                   \
    {   const int k0 = 0; const uint32_t bo = 0;                              \
        _Pragma("unroll")                                                     \
        for (int p = 0; p < 4; ++p) {                                         \
            int row = f_row + 32*p;                                           \
            uint32_t so = SWZ((uint32_t)(row*128 + f_c*16));                  \
            CP16(smb + bo + so,          (A_PTR_EXPR));                       \
            CP16(smb + bo + 16384u + so, (B_PTR_EXPR));                       \
        }                                                                     \
        CP_COMMIT();                                                          \
    }                                                                         \
    int bb = 0;                                                               \
    for (int kc = 0; kc < 32; ++kc) {                                         \
        CP_WAIT0();                                                           \
        __syncthreads();                                                      \
        if (kc < 31) {                                                        \
            const int k0 = (kc + 1) * 32;                                     \
            const uint32_t bo = (uint32_t)((bb ^ 1) * 32768);                 \
            _Pragma("unroll")                                                 \
            for (int p = 0; p < 4; ++p) {                                     \
                int row = f_row + 32*p;                                       \
                uint32_t so = SWZ((uint32_t)(row*128 + f_c*16));              \
                CP16(smb + bo + so,          (A_PTR_EXPR));                   \
                CP16(smb + bo + 16384u + so, (B_PTR_EXPR));                   \
            }                                                                 \
            CP_COMMIT();                                                      \
        }                                                                     \
        const uint32_t bo = (uint32_t)(bb * 32768);                           \
        _Pragma("unroll")                                                     \
        for (int k8 = 0; k8 < 4; ++k8) {                                      \
            const uint32_t ofsA = bo + ((((uint32_t)(2*k8) + aSel) ^ sw) << 4);\
            const uint32_t ofsB = bo + ((((uint32_t)(2*k8) + bSel) ^ sw) << 4);\
            unsigned a0[4], a1[4];                                            \
            LDSM4(a0[0], a0[1], a0[2], a0[3], aBase[0] + ofsA);               \
            LDSM4(a1[0], a1[1], a1[2], a1[3], aBase[1] + ofsA);               \
            _Pragma("unroll")                                                 \
            for (int q = 0; q < 4; ++q) {                                     \
                unsigned b0, b1, b2, b3;                                      \
                LDSM4(b0, b1, b2, b3, bBase[q] + ofsB);                       \
                mma8(acc[0][2*q],   a0, b0, b1);                              \
                mma8(acc[1][2*q],   a1, b0, b1);                              \
                mma8(acc[0][2*q+1], a0, b2, b3);                              \
                mma8(acc[1][2*q+1], a1, b2, b3);                              \
            }                                                                 \
        }                                                                     \
        bb ^= 1;                                                              \
    }

// ---------------------------------------------------------------------------
// Fused QKV projection. grid (64, 24): y -> mat (y>>3), head-pair (y&7).
// Q: pre-scaled by 0.125*log2e + tf32-rounded. K: tf32-rounded.
// V: transposed (B,H,E,S) + tf32-rounded.
// ---------------------------------------------------------------------------
__global__ __launch_bounds__(256, 2) void qkv_kernel(
    const float* __restrict__ bQ, const float* __restrict__ bK,
    const float* __restrict__ bV)
{
    const int m0  = blockIdx.x * 128;
    const int mat = blockIdx.y >> 3;
    const int h0  = (blockIdx.y & 7) * 2;
    const float* WT = ((mat==0) ? g_WTq : (mat==1) ? g_WTk : g_WTv)
                      + (size_t)h0 * E_ * D_;
    const float* bias = ((mat==0) ? bQ : (mat==1) ? bK : bV) + h0*E_;

    GEMM_BODY(
        (g_Xr + (size_t)(m0 + row)*D_ + k0 + f_c*4),
        (WT   + (size_t)row*D_        + k0 + f_c*4))

    if (mat == 2) {
        // V: transposed scatter to g_Vt (B,H,E,S), tf32-rounded
#pragma unroll
        for (int nf = 0; nf < 8; ++nf) {
            int n = wn + nf*8 + 2*t;
            int h = n >> 6, e = n & 63;
            float bi0 = bias[h*E_ + e], bi1 = bias[h*E_ + e + 1];
#pragma unroll
            for (int mf = 0; mf < 2; ++mf) {
                int m = m0 + wm + mf*16 + g;
                int bidx = m >> 11, s = m & (S_-1);
                float* base = g_Vt + (((size_t)(bidx*H_ + h0 + h)*E_ + e)*S_) + s;
                base[0]      = tf32r(acc[mf][nf][0] + bi0);
                base[8]      = tf32r(acc[mf][nf][2] + bi0);
                base[S_]     = tf32r(acc[mf][nf][1] + bi1);
                base[S_ + 8] = tf32r(acc[mf][nf][3] + bi1);
            }
        }
    } else {
        float* out = (mat == 0) ? g_Q : g_K;
        const float scl = (mat == 0) ? QSCL : 1.0f;
#pragma unroll
        for (int nf = 0; nf < 8; ++nf) {
            int n = wn + nf*8 + 2*t;
            int h = n >> 6, e = n & 63;
            float bi0 = bias[h*E_ + e], bi1 = bias[h*E_ + e + 1];
#pragma unroll
            for (int mf = 0; mf < 2; ++mf) {
                int m = m0 + wm + mf*16 + g;
                int bidx = m >> 11, s = m & (S_-1);
                float* r0 = out + ((size_t)(bidx*H_ + h0 + h)*S_ + s)*E_ + e;
                *(float2*)r0 = make_float2(tf32r((acc[mf][nf][0] + bi0)*scl),
                                           tf32r((acc[mf][nf][1] + bi1)*scl));
                *(float2*)(r0 + 8*E_) = make_float2(tf32r((acc[mf][nf][2] + bi0)*scl),
                                                    tf32r((acc[mf][nf][3] + bi1)*scl));
            }
        }
    }
}

// ---------------------------------------------------------------------------
// Output projection. grid (64, 8). g_Z pre-rounded by att epilogue.
// ---------------------------------------------------------------------------
__global__ __launch_bounds__(256, 2) void outproj_kernel(
    const float* __restrict__ bO, float* __restrict__ outp)
{
    const int m0 = blockIdx.x * 128;
    const int n0 = blockIdx.y * 128;

    GEMM_BODY(
        (g_Z   + (size_t)(m0 + row)*D_ + k0 + f_c*4),
        (g_WTo + (size_t)(n0 + row)*D_ + k0 + f_c*4))

#pragma unroll
    for (int nf = 0; nf < 8; ++nf) {
        int col = n0 + wn + nf*8 + 2*t;
        float bi0 = bO[col], bi1 = bO[col+1];
#pragma unroll
        for (int mf = 0; mf < 2; ++mf) {
            int m = m0 + wm + mf*16 + g;
            *(float2*)&outp[(size_t)m*D_ + col] =
                make_float2(acc[mf][nf][0] + bi0, acc[mf][nf][1] + bi1);
            *(float2*)&outp[(size_t)(m+8)*D_ + col] =
                make_float2(acc[mf][nf][2] + bi0, acc[mf][nf][3] + bi1);
        }
    }
}

// ---------------------------------------------------------------------------
// Flash attention (causal), tf32 MMA + ldmatrix + cp.async double buffering.
// Block = 128 queries x (b,h), 8 warps x 16 q-rows, 64-key tiles.
// Smem: K 2x16KB, Vt 2x16KB, P/Q stage 8x4KB = 96KB -> 2 CTAs/SM.
// ---------------------------------------------------------------------------
#define ATT_SMEM_BYTES 98304

__global__ __launch_bounds__(256, 2) void att_kernel()
{
    extern __shared__ char smc[];
    char* Pp  = smc + 65536;    // 8 warps x 4096
    const uint32_t Ku  = smem_u32(smc);            // 2 bufs x 16384
    const uint32_t Vtu = Ku + 32768;               // 2 bufs x 16384
    const uint32_t Pu  = Ku + 65536;

    const int tid  = threadIdx.x;
    const int warp = tid >> 5;
    const int lane = tid & 31;
    const int t    = lane & 3;
    const int g    = lane >> 2;
    const int wq   = warp * 16;
    const uint32_t sw   = (uint32_t)(lane & 7);
    const uint32_t aSel = (uint32_t)((lane >> 4) & 1);
    const uint32_t bSel = (uint32_t)((lane >> 3) & 1);

    const int qt = gridDim.x - 1 - blockIdx.x;   // big tiles first
    const int h  = blockIdx.y;
    const int b  = blockIdx.z;
    const size_t bh  = (size_t)(b*H_ + h) * S_;
    const size_t bhv = (size_t)(b*H_ + h) * E_ * S_;
    const int q0 = qt * 128;

    const int l_row = tid >> 4, l_c4 = tid & 15;
    const uint32_t fill_off = (uint32_t)((l_c4>>3)*8192);

    auto cpFill = [&](int bbuf, int kt) {
        const float* Kb = g_K + (bh + kt*64) * E_;
        const float* Vb = g_Vt + bhv + kt*64;
        const uint32_t bo = (uint32_t)(bbuf*16384) + fill_off;
#pragma unroll
        for (int p = 0; p < 4; ++p) {
            int row = l_row + p*16;
            uint32_t so = bo + SWZ((uint32_t)(row*128 + (l_c4&7)*16));
            CP16(Ku  + so, Kb + row*E_ + l_c4*4);
            CP16(Vtu + so, Vb + (size_t)row*S_ + l_c4*4);
        }
        CP_COMMIT();
    };
    cpFill(0, 0);

    // ---- stage Q (pre-scaled/rounded) into P region, pull fragments
    {
        const float* Qb = g_Q + (bh + q0) * E_;
#pragma unroll
        for (int p = 0; p < 8; ++p) {
            int idx = tid + 256*p;
            int row = idx >> 4, c4 = idx & 15;
            float4 v = *(const float4*)(Qb + row*E_ + c4*4);
            *(float4*)(Pp + (row>>4)*4096 + (c4>>3)*2048
                       + SWZ((uint32_t)((row&15)*128 + (c4&7)*16))) = v;
        }
    }
    __syncthreads();
    const uint32_t pw = Pu + warp*4096;
    unsigned qf[8][4];
#pragma unroll
    for (int d8 = 0; d8 < 8; ++d8) {
        uint32_t addr = pw + (uint32_t)((d8>>2)*2048) + (uint32_t)((lane&15)*128)
                        + ((((uint32_t)(2*(d8&3)) + aSel) ^ sw) << 4);
        LDSM4(qf[d8][0], qf[d8][1], qf[d8][2], qf[d8][3], addr);
    }

    uint32_t kB[4], vB[4];
#pragma unroll
    for (int q = 0; q < 4; ++q) {
        uint32_t r = (uint32_t)(q*16 + ((lane>>4)&1)*8 + (lane&7)) * 128u;
        kB[q] = Ku  + r;
        vB[q] = Vtu + r;
    }

    float O[8][4];
#pragma unroll
    for (int nf = 0; nf < 8; ++nf)
#pragma unroll
        for (int c = 0; c < 4; ++c) O[nf][c] = 0.f;
    float mA = -1e30f, mB = -1e30f, lA = 0.f, lB = 0.f;

    const int rowA = q0 + wq + g;
    const int rowB = rowA + 8;
    const int tmax = 2*qt + 1;
    int bb = 0;

    for (int kt = 0; kt <= tmax; ++kt) {
        CP_WAIT0();
        __syncthreads();
        if (kt < tmax) cpFill(bb ^ 1, kt + 1);
        const uint32_t bo = (uint32_t)(bb * 16384);

        // ---- S = Q K^T
        float sv[8][4];
#pragma unroll
        for (int nf = 0; nf < 8; ++nf)
#pragma unroll
            for (int c = 0; c < 4; ++c) sv[nf][c] = 0.f;
#pragma unroll
        for (int d8 = 0; d8 < 8; ++d8) {
            uint32_t ofs = bo + ((((uint32_t)(2*(d8&3)) + bSel) ^ sw) << 4)
                           + (uint32_t)((d8>>2)*8192);
#pragma unroll
            for (int q = 0; q < 4; ++q) {
                unsigned b0, b1, b2, b3;
                LDSM4(b0, b1, b2, b3, kB[q] + ofs);
                mma8(sv[2*q],   qf[d8], b0, b1);
                mma8(sv[2*q+1], qf[d8], b2, b3);
            }
        }

        // ---- causal mask (scale+log2e pre-folded into Q)
        const bool edge = (kt >= 2*qt);
        if (edge) {
#pragma unroll
            for (int nf = 0; nf < 8; ++nf) {
                int cb = kt*64 + nf*8 + 2*t;
                if (cb   > rowA) sv[nf][0] = -1e30f;
                if (cb+1 > rowA) sv[nf][1] = -1e30f;
                if (cb   > rowB) sv[nf][2] = -1e30f;
                if (cb+1 > rowB) sv[nf][3] = -1e30f;
            }
        }

        // ---- warp-local online softmax (base-2)
        float rmA = -1e30f, rmB = -1e30f;
#pragma unroll
        for (int nf = 0; nf < 8; ++nf) {
            rmA = fmaxf(rmA, fmaxf(sv[nf][0], sv[nf][1]));
            rmB = fmaxf(rmB, fmaxf(sv[nf][2], sv[nf][3]));
        }
        rmA = fmaxf(rmA, __shfl_xor_sync(0xffffffffu, rmA, 1));
        rmA = fmaxf(rmA, __shfl_xor_sync(0xffffffffu, rmA, 2));
        rmB = fmaxf(rmB, __shfl_xor_sync(0xffffffffu, rmB, 1));
        rmB = fmaxf(rmB, __shfl_xor_sync(0xffffffffu, rmB, 2));

        float mnA = fmaxf(mA, rmA), mnB = fmaxf(mB, rmB);
        float corrA = exp2f(mA - mnA), corrB = exp2f(mB - mnB);
        float rsA = 0.f, rsB = 0.f;
#pragma unroll
        for (int nf = 0; nf < 8; ++nf) {
            float p0 = exp2f(sv[nf][0] - mnA);
            float p1 = exp2f(sv[nf][1] - mnA);
            float p2 = exp2f(sv[nf][2] - mnB);
            float p3 = exp2f(sv[nf][3] - mnB);
            rsA += p0 + p1; rsB += p2 + p3;
            uint32_t poff = (uint32_t)((nf>>2)*2048);
            uint32_t in0 = (uint32_t)(((nf&3)*8 + 2*t)*4);
            *(float2*)((char*)Pp + (pw - Pu) + poff
                       + SWZ((uint32_t)(g*128) + in0)) =
                make_float2(tf32r(p0), tf32r(p1));
            *(float2*)((char*)Pp + (pw - Pu) + poff
                       + SWZ((uint32_t)((g+8)*128) + in0)) =
                make_float2(tf32r(p2), tf32r(p3));
        }
        rsA += __shfl_xor_sync(0xffffffffu, rsA, 1);
        rsA += __shfl_xor_sync(0xffffffffu, rsA, 2);
        rsB += __shfl_xor_sync(0xffffffffu, rsB, 1);
        rsB += __shfl_xor_sync(0xffffffffu, rsB, 2);
        lA = lA*corrA + rsA; mA = mnA;
        lB = lB*corrB + rsB; mB = mnB;
#pragma unroll
        for (int nf = 0; nf < 8; ++nf) {
            O[nf][0] *= corrA; O[nf][1] *= corrA;
            O[nf][2] *= corrB; O[nf][3] *= corrB;
        }
        __syncwarp();

        // ---- O += P V
#pragma unroll
        for (int kk = 0; kk < 8; ++kk) {
            uint32_t pofs = pw + (uint32_t)((kk>>2)*2048)
                            + (uint32_t)((lane&15)*128)
                            + ((((uint32_t)(2*(kk&3)) + aSel) ^ sw) << 4);
            unsigned pa[4];
            LDSM4(pa[0], pa[1], pa[2], pa[3], pofs);
            uint32_t ofs = bo + ((((uint32_t)(2*(kk&3)) + bSel) ^ sw) << 4)
                           + (uint32_t)((kk>>2)*8192);
#pragma unroll
            for (int q = 0; q < 4; ++q) {
                unsigned b0, b1, b2, b3;
                LDSM4(b0, b1, b2, b3, vB[q] + ofs);
                mma8(O[2*q],   pa, b0, b1);
                mma8(O[2*q+1], pa, b2, b3);
            }
        }
        bb ^= 1;
    }

    // ---- epilogue: normalize + write z (B,S,H*E), tf32-rounded for outproj
    float invA = 1.0f / lA, invB = 1.0f / lB;
    float* zA = g_Z + (size_t)(b*S_ + q0 + wq + g    )*(H_*E_) + h*E_;
    float* zB = g_Z + (size_t)(b*S_ + q0 + wq + g + 8)*(H_*E_) + h*E_;
#pragma unroll
    for (int nf = 0; nf < 8; ++nf) {
        int col = nf*8 + 2*t;
        *(float2*)(zA + col) = make_float2(tf32r(O[nf][0]*invA), tf32r(O[nf][1]*invA));
        *(float2*)(zB + col) = make_float2(tf32r(O[nf][2]*invB), tf32r(O[nf][3]*invB));
    }
}

// ---------------------------------------------------------------------------
extern "C" void kernel_launch(void* const* d_in, const int* in_sizes, int n_in,
                              void* d_out, int out_size)
{
    const float* x   = (const float*)d_in[0];
    const float* W_Q = (const float*)d_in[1];
    const float* b_Q = (const float*)d_in[2];
    const float* W_K = (const float*)d_in[3];
    const float* b_K = (const float*)d_in[4];
    const float* W_V = (const float*)d_in[5];
    const float* b_V = (const float*)d_in[6];
    const float* W_O = (const float*)d_in[7];
    const float* b_O = (const float*)d_in[8];
    float* out = (float*)d_out;

    cudaFuncSetAttribute(att_kernel,
        cudaFuncAttributeMaxDynamicSharedMemorySize, ATT_SMEM_BYTES);
    cudaFuncSetAttribute(qkv_kernel,
        cudaFuncAttributeMaxDynamicSharedMemorySize, GEMM_SMEM_BYTES);
    cudaFuncSetAttribute(outproj_kernel,
        cudaFuncAttributeMaxDynamicSharedMemorySize, GEMM_SMEM_BYTES);

    float *wtq, *wtk, *wtv, *wto;
    cudaGetSymbolAddress((void**)&wtq, g_WTq);
    cudaGetSymbolAddress((void**)&wtk, g_WTk);
    cudaGetSymbolAddress((void**)&wtv, g_WTv);
    cudaGetSymbolAddress((void**)&wto, g_WTo);

    round_x<<<(M_*D_/4)/256, 256>>>(x);
    dim3 tb(32, 8);
    transpose_rc<<<dim3(32, 2, 16), tb>>>(W_Q, wtq, D_, E_);
    transpose_rc<<<dim3(32, 2, 16), tb>>>(W_K, wtk, D_, E_);
    transpose_rc<<<dim3(32, 2, 16), tb>>>(W_V, wtv, D_, E_);
    transpose_rc<<<dim3(32, 32, 1), tb>>>(W_O, wto, D_, D_);

    dim3 gqkv(M_/128, 24);
    qkv_kernel<<<gqkv, 256, GEMM_SMEM_BYTES>>>(b_Q, b_K, b_V);

    dim3 gatt(S_/128, H_, B_);
    att_kernel<<<gatt, 256, ATT_SMEM_BYTES>>>();

    dim3 gout(M_/128, D_/128);
    outproj_kernel<<<gout, 256, GEMM_SMEM_BYTES>>>(b_O, out);
}